// round 14
// baseline (speedup 1.0000x reference)
#include <cuda_runtime.h>
#include <cuda_bf16.h>
#include <math.h>
#include <stdint.h>

// ---------------- problem constants ----------------
#define BATCH 64
#define HH 56
#define WW_ 56
#define CDIM 128
#define L_TOK (HH * WW_)            // 3136
#define M_TOK (BATCH * L_TOK)       // 200704
#define NHEAD 4
#define HDIM 32
#define WS 7
#define NWIN_SIDE 8
#define NTOK 49
#define SHIFT 3
#define HIDDEN 512

// weight-transpose buffer offsets (bf16 [N,K] layouts)
#define WQ_OFF 0            // 384*128
#define WP_OFF 49152        // 128*128
#define W1_OFF 65536        // 512*128
#define W2_OFF 131072       // 128*512
#define WT_TOTAL 196608

// ---------------- scratch ----------------
__device__ __nv_bfloat16 g_attnb[(size_t)M_TOK * CDIM];
__device__ float g_x1[(size_t)M_TOK * CDIM];
__device__ __nv_bfloat16 g_wT[WT_TOTAL];

__device__ __forceinline__ uint32_t smem_u32(const void* p) {
    uint32_t a;
    asm("{ .reg .u64 t; cvta.to.shared.u64 t, %1; cvt.u32.u64 %0, t; }" : "=r"(a) : "l"(p));
    return a;
}
__device__ __forceinline__ uint32_t pack_bf2(float a, float b) {
    __nv_bfloat162 t = __floats2bfloat162_rn(a, b);
    return *reinterpret_cast<uint32_t*>(&t);
}
__device__ __forceinline__ void cp16(uint32_t dst, const void* src) {
    asm volatile("cp.async.cg.shared.global [%0], [%1], 16;" :: "r"(dst), "l"(src));
}
#define CP_COMMIT() asm volatile("cp.async.commit_group;" ::: "memory")
#define CP_WAIT(N)  asm volatile("cp.async.wait_group %0;" :: "n"(N) : "memory")

#define LDSM_X4(r0, r1, r2, r3, addr) \
    asm volatile("ldmatrix.sync.aligned.m8n8.x4.shared.b16 {%0,%1,%2,%3}, [%4];" \
        : "=r"(r0), "=r"(r1), "=r"(r2), "=r"(r3) : "r"(addr))

#define MMA_BF16(c, a, b0, b1) \
    asm volatile("mma.sync.aligned.m16n8k16.row.col.f32.bf16.bf16.f32 " \
        "{%0,%1,%2,%3}, {%4,%5,%6,%7}, {%8,%9}, {%0,%1,%2,%3};" \
        : "+f"((c)[0]), "+f"((c)[1]), "+f"((c)[2]), "+f"((c)[3]) \
        : "r"((a)[0]), "r"((a)[1]), "r"((a)[2]), "r"((a)[3]), "r"(b0), "r"(b1))

// ---------------- weight transpose + bf16 convert ----------------
__global__ void __launch_bounds__(256) convert_w_kernel(
    const float* __restrict__ qkv_w, const float* __restrict__ proj_w,
    const float* __restrict__ fc1_w, const float* __restrict__ fc2_w,
    __nv_bfloat16* __restrict__ wT)
{
    int i = blockIdx.x * 256 + threadIdx.x;
    if (i < WQ_OFF + 49152) {
        int j = i - WQ_OFF; int n = j / 128, k = j % 128;
        wT[i] = __float2bfloat16(qkv_w[k * 384 + n]);
    } else if (i < WP_OFF + 16384) {
        int j = i - WP_OFF; int n = j / 128, k = j % 128;
        wT[i] = __float2bfloat16(proj_w[k * 128 + n]);
    } else if (i < W1_OFF + 65536) {
        int j = i - W1_OFF; int n = j / 128, k = j % 128;
        wT[i] = __float2bfloat16(fc1_w[k * 512 + n]);
    } else if (i < W2_OFF + 65536) {
        int j = i - W2_OFF; int n = j / 512, k = j % 512;
        wT[i] = __float2bfloat16(fc2_w[k * 128 + n]);
    }
}

// =========================================================================
// Fused front half: LN1(+shift+gather) + QKV + attention. (R13, best)
// =========================================================================
#define AS 136
#define SVT 72
#define SPP 72
#define UNI_ELEM 18432
#define ATTF_BASE (64*AS*2 + 36864 + 64*AS*2 + 64*AS*2 + 128*SVT*2)
#define ATTF_SMEM (ATTF_BASE + 192 + 2704)

__global__ void __launch_bounds__(256) attn_fused(
    const float* __restrict__ X, const __nv_bfloat16* __restrict__ wq,
    const float* __restrict__ lng, const float* __restrict__ lnb,
    const float* __restrict__ qkvbias, const float* __restrict__ bias_table,
    __nv_bfloat16* __restrict__ out)
{
    extern __shared__ __align__(16) char dsm[];
    __nv_bfloat16* sX  = (__nv_bfloat16*)dsm;
    __nv_bfloat16* uni = sX + 64 * AS;
    __nv_bfloat16* sW  = uni;
    __nv_bfloat16* sP  = uni;
    __nv_bfloat16* sQ  = uni + UNI_ELEM;
    __nv_bfloat16* sK  = sQ + 64 * AS;
    __nv_bfloat16* sVt = sK + 64 * AS;
    unsigned char* sGrp = (unsigned char*)(dsm + ATTF_BASE);
    signed char*   sDiv = (signed char*)(sGrp + 64);
    signed char*   sMod = (signed char*)(sDiv + 64);
    float*         sBias = (float*)(dsm + ATTF_BASE + 192);

    const int tid = threadIdx.x, wid = tid >> 5, lane = tid & 31;
    const int win = blockIdx.x;
    const int wloc = win & 63, wh = wloc >> 3, wwi = wloc & 7;

    const int mat = lane >> 3;
    const int aRowOff = (lane & 7) + (mat & 1) * 8;
    const int aKOff = (mat >> 1) * 8;
    const int bRowOff = (lane & 7) + ((mat >> 1) & 1) * 8;
    const int bKOff = (mat & 1) * 8;
    const int g4 = lane >> 2, t4 = lane & 3;

    const uint32_t uX = smem_u32(sX), uW = smem_u32(sW);
    const uint32_t uQ = smem_u32(sQ), uK = smem_u32(sK), uVt = smem_u32(sVt);

    {
        #pragma unroll
        for (int it = 0; it < 8; ++it) {
            int i = tid + it * 256;
            int r = i >> 4, qq = i & 15;
            cp16(uW + (uint32_t)(r * AS + qq * 8) * 2, wq + (size_t)r * 128 + qq * 8);
        }
        CP_COMMIT();
    }

    for (int i = tid; i < 676; i += 256) sBias[i] = bias_table[i];

    {
        const int row8 = tid >> 3;
        const int lane8 = tid & 7;
        const float4 gv[4] = {
            *(const float4*)&lng[lane8 * 16 + 0],  *(const float4*)&lng[lane8 * 16 + 4],
            *(const float4*)&lng[lane8 * 16 + 8],  *(const float4*)&lng[lane8 * 16 + 12] };
        const float4 bv[4] = {
            *(const float4*)&lnb[lane8 * 16 + 0],  *(const float4*)&lnb[lane8 * 16 + 4],
            *(const float4*)&lnb[lane8 * 16 + 8],  *(const float4*)&lnb[lane8 * 16 + 12] };
        #pragma unroll
        for (int pass = 0; pass < 2; ++pass) {
            const int row = pass * 32 + row8;
            const int trow = (row < NTOK) ? row : (NTOK - 1);
            const int ih = trow / WS, iw = trow - ih * WS;
            int h = wh * WS + ih + SHIFT; if (h >= HH) h -= HH;
            int w = wwi * WS + iw + SHIFT; if (w >= WW_) w -= WW_;
            const int srow = (win >> 6) * L_TOK + h * WW_ + w;
            const float4* xr = (const float4*)(X + (size_t)srow * CDIM) + lane8 * 4;
            float4 v[4];
            float sum = 0.f, sq = 0.f;
            #pragma unroll
            for (int j = 0; j < 4; ++j) {
                v[j] = xr[j];
                sum += v[j].x + v[j].y + v[j].z + v[j].w;
                sq  += v[j].x * v[j].x + v[j].y * v[j].y + v[j].z * v[j].z + v[j].w * v[j].w;
            }
            #pragma unroll
            for (int o = 1; o < 8; o <<= 1) {
                sum += __shfl_xor_sync(0xffffffffu, sum, o);
                sq  += __shfl_xor_sync(0xffffffffu, sq, o);
            }
            const float mean = sum * (1.0f / 128.0f);
            const float var = sq * (1.0f / 128.0f) - mean * mean;
            const float inv = rsqrtf(var + 1e-5f);
            uint4 o0, o1;
            o0.x = pack_bf2((v[0].x - mean) * inv * gv[0].x + bv[0].x,
                            (v[0].y - mean) * inv * gv[0].y + bv[0].y);
            o0.y = pack_bf2((v[0].z - mean) * inv * gv[0].z + bv[0].z,
                            (v[0].w - mean) * inv * gv[0].w + bv[0].w);
            o0.z = pack_bf2((v[1].x - mean) * inv * gv[1].x + bv[1].x,
                            (v[1].y - mean) * inv * gv[1].y + bv[1].y);
            o0.w = pack_bf2((v[1].z - mean) * inv * gv[1].z + bv[1].z,
                            (v[1].w - mean) * inv * gv[1].w + bv[1].w);
            o1.x = pack_bf2((v[2].x - mean) * inv * gv[2].x + bv[2].x,
                            (v[2].y - mean) * inv * gv[2].y + bv[2].y);
            o1.y = pack_bf2((v[2].z - mean) * inv * gv[2].z + bv[2].z,
                            (v[2].w - mean) * inv * gv[2].w + bv[2].w);
            o1.z = pack_bf2((v[3].x - mean) * inv * gv[3].x + bv[3].x,
                            (v[3].y - mean) * inv * gv[3].y + bv[3].y);
            o1.w = pack_bf2((v[3].z - mean) * inv * gv[3].z + bv[3].z,
                            (v[3].w - mean) * inv * gv[3].w + bv[3].w);
            *(uint4*)&sX[row * AS + lane8 * 16 + 0] = o0;
            *(uint4*)&sX[row * AS + lane8 * 16 + 8] = o1;
        }
    }
    if (tid < 64) {
        int ih = tid / 7, iw = tid % 7;
        sDiv[tid] = (signed char)ih;
        sMod[tid] = (signed char)iw;
        int hs = wh * WS + ih, ws = wwi * WS + iw;
        int gh = hs < (HH - WS) ? 0 : (hs < (HH - SHIFT) ? 1 : 2);
        int gw = ws < (WW_ - WS) ? 0 : (ws < (WW_ - SHIFT) ? 1 : 2);
        sGrp[tid] = (unsigned char)(gh * 3 + gw);
    }

    const int mBq = (wid & 1) * 32;
    const int nBq = (wid >> 1) * 32;
    const float scale = 0.17677669529663689f;

    for (int p = 0; p < 3; ++p) {
        CP_WAIT(0);
        __syncthreads();

        float qa[2][4][4];
        #pragma unroll
        for (int i = 0; i < 2; ++i)
            #pragma unroll
            for (int j = 0; j < 4; ++j)
                #pragma unroll
                for (int t = 0; t < 4; ++t) qa[i][j][t] = 0.0f;

        #pragma unroll
        for (int kk = 0; kk < 8; ++kk) {
            const int k0 = kk * 16;
            uint32_t a[2][4];
            #pragma unroll
            for (int mf = 0; mf < 2; ++mf) {
                uint32_t addr = uX + ((mBq + mf * 16 + aRowOff) * AS + k0 + aKOff) * 2;
                LDSM_X4(a[mf][0], a[mf][1], a[mf][2], a[mf][3], addr);
            }
            #pragma unroll
            for (int nn = 0; nn < 2; ++nn) {
                uint32_t b0, b1, b2, b3;
                uint32_t addr = uW + ((nBq + nn * 16 + bRowOff) * AS + k0 + bKOff) * 2;
                LDSM_X4(b0, b1, b2, b3, addr);
                #pragma unroll
                for (int mf = 0; mf < 2; ++mf) {
                    MMA_BF16(qa[mf][nn * 2 + 0], a[mf], b0, b1);
                    MMA_BF16(qa[mf][nn * 2 + 1], a[mf], b2, b3);
                }
            }
        }
        __syncthreads();

        if (p < 2) {
            #pragma unroll
            for (int it = 0; it < 8; ++it) {
                int i = tid + it * 256;
                int r = i >> 4, qq = i & 15;
                cp16(uW + (uint32_t)(r * AS + qq * 8) * 2,
                     wq + (size_t)(p + 1) * 16384 + (size_t)r * 128 + qq * 8);
            }
            CP_COMMIT();
        }

        #pragma unroll
        for (int mf = 0; mf < 2; ++mf)
            #pragma unroll
            for (int rr = 0; rr < 2; ++rr) {
                const int m = mBq + mf * 16 + g4 + rr * 8;
                #pragma unroll
                for (int nf = 0; nf < 4; ++nf) {
                    const int n = nBq + nf * 8 + 2 * t4;
                    const float2 bf2 = *(const float2*)&qkvbias[p * 128 + n];
                    float v0 = qa[mf][nf][rr * 2 + 0] + bf2.x;
                    float v1 = qa[mf][nf][rr * 2 + 1] + bf2.y;
                    if (p == 0) {
                        *(uint32_t*)&sQ[m * AS + n] = pack_bf2(v0 * scale, v1 * scale);
                    } else if (p == 1) {
                        *(uint32_t*)&sK[m * AS + n] = pack_bf2(v0, v1);
                    } else {
                        sVt[n * SVT + m]       = __float2bfloat16(v0);
                        sVt[(n + 1) * SVT + m] = __float2bfloat16(v1);
                    }
                }
            }
    }
    __syncthreads();

    const int h = wid >> 1;
    const int mBase = (wid & 1) * 32;
    const int colQ = h * 32;
    __nv_bfloat16* sPw = sP + wid * 32 * SPP;
    const uint32_t uP = smem_u32(sPw);

    float acc[2][8][4];
    #pragma unroll
    for (int i = 0; i < 2; ++i)
        #pragma unroll
        for (int j = 0; j < 8; ++j)
            #pragma unroll
            for (int t = 0; t < 4; ++t) acc[i][j][t] = 0.0f;

    uint32_t a[2][2][4];
    #pragma unroll
    for (int mf = 0; mf < 2; ++mf)
        #pragma unroll
        for (int ks = 0; ks < 2; ++ks) {
            uint32_t addr = uQ + ((mBase + mf * 16 + aRowOff) * AS + colQ + ks * 16 + aKOff) * 2;
            LDSM_X4(a[mf][ks][0], a[mf][ks][1], a[mf][ks][2], a[mf][ks][3], addr);
        }
    #pragma unroll
    for (int nb = 0; nb < 4; ++nb) {
        uint32_t b[2][4];
        #pragma unroll
        for (int ks = 0; ks < 2; ++ks) {
            uint32_t addr = uK + ((nb * 16 + bRowOff) * AS + colQ + ks * 16 + bKOff) * 2;
            LDSM_X4(b[ks][0], b[ks][1], b[ks][2], b[ks][3], addr);
        }
        #pragma unroll
        for (int ks = 0; ks < 2; ++ks)
            #pragma unroll
            for (int mf = 0; mf < 2; ++mf) {
                MMA_BF16(acc[mf][nb * 2 + 0], a[mf][ks], b[ks][0], b[ks][1]);
                MMA_BF16(acc[mf][nb * 2 + 1], a[mf][ks], b[ks][2], b[ks][3]);
            }
    }

    int ii[2][2];
    #pragma unroll
    for (int mf = 0; mf < 2; ++mf)
        #pragma unroll
        for (int rr = 0; rr < 2; ++rr) ii[mf][rr] = mBase + mf * 16 + g4 + rr * 8;

    float mx[2][2] = {{-1e30f, -1e30f}, {-1e30f, -1e30f}};
    #pragma unroll
    for (int mf = 0; mf < 2; ++mf)
        #pragma unroll
        for (int nf = 0; nf < 8; ++nf)
            #pragma unroll
            for (int e = 0; e < 4; ++e) {
                int rr = e >> 1;
                int jj = nf * 8 + 2 * t4 + (e & 1);
                float s;
                if (jj < NTOK) {
                    int i0 = ii[mf][rr];
                    int i0c = (i0 < NTOK) ? i0 : (NTOK - 1);
                    int dh = sDiv[i0c] - sDiv[jj] + 6;
                    int dw = sMod[i0c] - sMod[jj] + 6;
                    float bv = sBias[(dh * 13 + dw) * NHEAD + h];
                    float mk = (sGrp[i0c] != sGrp[jj]) ? -100.0f : 0.0f;
                    s = acc[mf][nf][e] + bv + mk;
                } else {
                    s = -1e30f;
                }
                acc[mf][nf][e] = s;
                mx[mf][rr] = fmaxf(mx[mf][rr], s);
            }
    #pragma unroll
    for (int mf = 0; mf < 2; ++mf)
        #pragma unroll
        for (int rr = 0; rr < 2; ++rr) {
            float m = mx[mf][rr];
            m = fmaxf(m, __shfl_xor_sync(0xffffffffu, m, 1));
            m = fmaxf(m, __shfl_xor_sync(0xffffffffu, m, 2));
            mx[mf][rr] = m;
        }

    float sm[2][2] = {{0.f, 0.f}, {0.f, 0.f}};
    #pragma unroll
    for (int mf = 0; mf < 2; ++mf)
        #pragma unroll
        for (int nf = 0; nf < 8; ++nf)
            #pragma unroll
            for (int e = 0; e < 4; ++e) {
                int rr = e >> 1;
                float ev = __expf(acc[mf][nf][e] - mx[mf][rr]);
                acc[mf][nf][e] = ev;
                sm[mf][rr] += ev;
            }
    #pragma unroll
    for (int mf = 0; mf < 2; ++mf)
        #pragma unroll
        for (int rr = 0; rr < 2; ++rr) {
            float s = sm[mf][rr];
            s += __shfl_xor_sync(0xffffffffu, s, 1);
            s += __shfl_xor_sync(0xffffffffu, s, 2);
            sm[mf][rr] = s;
        }

    #pragma unroll
    for (int mf = 0; mf < 2; ++mf)
        #pragma unroll
        for (int rr = 0; rr < 2; ++rr) {
            int prow = mf * 16 + g4 + rr * 8;
            #pragma unroll
            for (int nf = 0; nf < 8; ++nf) {
                uint32_t u = pack_bf2(acc[mf][nf][rr * 2], acc[mf][nf][rr * 2 + 1]);
                *(uint32_t*)&sPw[prow * SPP + nf * 8 + 2 * t4] = u;
            }
        }
    __syncwarp();

    float acc2[2][4][4];
    #pragma unroll
    for (int i = 0; i < 2; ++i)
        #pragma unroll
        for (int j = 0; j < 4; ++j)
            #pragma unroll
            for (int t = 0; t < 4; ++t) acc2[i][j][t] = 0.0f;

    #pragma unroll
    for (int kc = 0; kc < 4; ++kc) {
        uint32_t a2[2][4], b2[2][4];
        #pragma unroll
        for (int mf = 0; mf < 2; ++mf) {
            uint32_t addr = uP + ((mf * 16 + aRowOff) * SPP + kc * 16 + aKOff) * 2;
            LDSM_X4(a2[mf][0], a2[mf][1], a2[mf][2], a2[mf][3], addr);
        }
        #pragma unroll
        for (int nb = 0; nb < 2; ++nb) {
            uint32_t addr = uVt + ((colQ + nb * 16 + bRowOff) * SVT + kc * 16 + bKOff) * 2;
            LDSM_X4(b2[nb][0], b2[nb][1], b2[nb][2], b2[nb][3], addr);
        }
        #pragma unroll
        for (int mf = 0; mf < 2; ++mf)
            #pragma unroll
            for (int nb = 0; nb < 2; ++nb) {
                MMA_BF16(acc2[mf][nb * 2 + 0], a2[mf], b2[nb][0], b2[nb][1]);
                MMA_BF16(acc2[mf][nb * 2 + 1], a2[mf], b2[nb][2], b2[nb][3]);
            }
    }

    #pragma unroll
    for (int mf = 0; mf < 2; ++mf)
        #pragma unroll
        for (int rr = 0; rr < 2; ++rr) {
            int i0 = ii[mf][rr];
            if (i0 < NTOK) {
                float inv = 1.0f / sm[mf][rr];
                __nv_bfloat16* orow = out + ((size_t)win * NTOK + i0) * CDIM + colQ;
                #pragma unroll
                for (int nf = 0; nf < 4; ++nf) {
                    float v0 = acc2[mf][nf][rr * 2 + 0] * inv;
                    float v1 = acc2[mf][nf][rr * 2 + 1] * inv;
                    *(uint32_t*)&orow[nf * 8 + 2 * t4] = pack_bf2(v0, v1);
                }
            }
        }
}

// ---------------- HMMA bf16 GEMM (proj): EPI1 only ----------------
#define SAS 72
__global__ void __launch_bounds__(256) gemm_proj(
    const __nv_bfloat16* __restrict__ A, const __nv_bfloat16* __restrict__ Bt,
    const float* __restrict__ bias, const float* __restrict__ res,
    float* __restrict__ C, int M, int N, int K)
{
    __shared__ __align__(16) __nv_bfloat16 sA[128 * SAS];
    __shared__ __align__(16) __nv_bfloat16 sB[128 * SAS];

    const int tid = threadIdx.x;
    const int wid = tid >> 5, lane = tid & 31;
    const int rowBase = blockIdx.y << 7;
    const int colBase = blockIdx.x << 7;

    const int mBase = (wid & 3) * 32;
    const int nBase = (wid >> 2) * 64;

    const uint32_t uA = smem_u32(sA), uB = smem_u32(sB);
    const int mat = lane >> 3;
    const int aRowOff = (lane & 7) + (mat & 1) * 8;
    const int aKOff = (mat >> 1) * 8;
    const int bRowOff = (lane & 7) + ((mat >> 1) & 1) * 8;
    const int bKOff = (mat & 1) * 8;

    float acc[2][8][4];
    #pragma unroll
    for (int i = 0; i < 2; ++i)
        #pragma unroll
        for (int j = 0; j < 8; ++j)
            #pragma unroll
            for (int t = 0; t < 4; ++t) acc[i][j][t] = 0.0f;

    const int nc = K >> 6;
    const int kq = K >> 3;

    for (int c = 0; c < nc; ++c) {
        const uint4* Ag = (const uint4*)(A + (size_t)rowBase * K + (size_t)c * 64);
        const uint4* Bg = (const uint4*)(Bt + (size_t)colBase * K + (size_t)c * 64);
        #pragma unroll
        for (int it = 0; it < 4; ++it) {
            int i = tid + it * 256;
            int row = i >> 3, q = i & 7;
            *(uint4*)&sA[row * SAS + q * 8] = Ag[(size_t)row * kq + q];
            *(uint4*)&sB[row * SAS + q * 8] = Bg[(size_t)row * kq + q];
        }
        __syncthreads();

        #pragma unroll
        for (int kk = 0; kk < 4; ++kk) {
            const int k0 = kk * 16;
            uint32_t a[2][4];
            #pragma unroll
            for (int mf = 0; mf < 2; ++mf) {
                uint32_t addr = uA + ((mBase + mf * 16 + aRowOff) * SAS + k0 + aKOff) * 2;
                LDSM_X4(a[mf][0], a[mf][1], a[mf][2], a[mf][3], addr);
            }
            #pragma unroll
            for (int nn = 0; nn < 4; ++nn) {
                uint32_t b0, b1, b2, b3;
                uint32_t addr = uB + ((nBase + nn * 16 + bRowOff) * SAS + k0 + bKOff) * 2;
                LDSM_X4(b0, b1, b2, b3, addr);
                #pragma unroll
                for (int mf = 0; mf < 2; ++mf) {
                    MMA_BF16(acc[mf][nn * 2 + 0], a[mf], b0, b1);
                    MMA_BF16(acc[mf][nn * 2 + 1], a[mf], b2, b3);
                }
            }
        }
        __syncthreads();
    }

    const int g4 = lane >> 2, t4 = lane & 3;
    #pragma unroll
    for (int mf = 0; mf < 2; ++mf)
        #pragma unroll
        for (int rr = 0; rr < 2; ++rr) {
            const int m = rowBase + mBase + mf * 16 + g4 + rr * 8;
            int win = m / NTOK, tt = m - win * NTOK;
            int bimg = win >> 6, wloc = win & 63;
            int wh = wloc >> 3, wwi = wloc & 7;
            int ih = tt / WS, iw = tt - ih * WS;
            int h = wh * WS + ih + SHIFT; if (h >= HH) h -= HH;
            int w = wwi * WS + iw + SHIFT; if (w >= WW_) w -= WW_;
            const int prow = bimg * L_TOK + h * WW_ + w;
            #pragma unroll
            for (int nf = 0; nf < 8; ++nf) {
                const int col = colBase + nBase + nf * 8 + 2 * t4;
                const float2 bf2 = *(const float2*)&bias[col];
                float v0 = acc[mf][nf][rr * 2 + 0] + bf2.x;
                float v1 = acc[mf][nf][rr * 2 + 1] + bf2.y;
                const size_t o = (size_t)prow * CDIM + col;
                float2 rv = *(const float2*)&res[o];
                float2 ov; ov.x = v0 + rv.x; ov.y = v1 + rv.y;
                *(float2*)&C[o] = ov;
            }
        }
}

// =========================================================================
// Fused MLP: LN2 + FC1 + GELU + FC2 + residual.
// Hidden chunks of 64 (8 chunks); 62.5 KB smem; 3 CTAs/SM target.
// =========================================================================
#define SMX 136
#define SHX 72
#define MLP_SMEM (64*SMX*2 + 64*SHX*2 + 64*SMX*2 + 128*SHX*2)   // 62,464 B

__global__ void __launch_bounds__(256, 3) mlp_fused(
    const float* __restrict__ X, const __nv_bfloat16* __restrict__ w1T,
    const __nv_bfloat16* __restrict__ w2T,
    const float* __restrict__ lng, const float* __restrict__ lnb,
    const float* __restrict__ b1, const float* __restrict__ b2,
    float* __restrict__ out)
{
    extern __shared__ __align__(16) char dsm[];
    __nv_bfloat16* sX  = (__nv_bfloat16*)dsm;          // [64][SMX]
    __nv_bfloat16* sH  = sX + 64 * SMX;                // [64][SHX]  (64 hidden cols)
    __nv_bfloat16* sW1 = sH + 64 * SHX;                // [64][SMX]  (64 hid rows x 128 K)
    __nv_bfloat16* sW2 = sW1 + 64 * SMX;               // [128][SHX] (128 out x 64 hid)

    const int tid = threadIdx.x;
    const int wid = tid >> 5, lane = tid & 31;
    const int rowBase = blockIdx.x << 6;

    const uint32_t uX = smem_u32(sX), uH = smem_u32(sH);
    const uint32_t uW1 = smem_u32(sW1), uW2 = smem_u32(sW2);

    // prefetch chunk 0 weights (overlaps LN)
    {
        #pragma unroll
        for (int it = 0; it < 4; ++it) {
            int i = tid + it * 256;
            int r = i >> 4, q = i & 15;
            cp16(uW1 + (uint32_t)(r * SMX + q * 8) * 2, w1T + (size_t)r * 128 + q * 8);
        }
        CP_COMMIT();
        #pragma unroll
        for (int it = 0; it < 4; ++it) {
            int i = tid + it * 256;
            int r = i >> 3, q = i & 7;
            cp16(uW2 + (uint32_t)(r * SHX + q * 8) * 2, w2T + (size_t)r * 512 + q * 8);
        }
        CP_COMMIT();
    }

    // ---- LN2 on 64 token rows ----
    {
        const int row8 = tid >> 3;
        const int lane8 = tid & 7;
        const float4 gv[4] = {
            *(const float4*)&lng[lane8 * 16 + 0],  *(const float4*)&lng[lane8 * 16 + 4],
            *(const float4*)&lng[lane8 * 16 + 8],  *(const float4*)&lng[lane8 * 16 + 12] };
        const float4 bv[4] = {
            *(const float4*)&lnb[lane8 * 16 + 0],  *(const float4*)&lnb[lane8 * 16 + 4],
            *(const float4*)&lnb[lane8 * 16 + 8],  *(const float4*)&lnb[lane8 * 16 + 12] };
        #pragma unroll
        for (int pass = 0; pass < 2; ++pass) {
            const int row = pass * 32 + row8;
            const float4* xr = (const float4*)(X + (size_t)(rowBase + row) * CDIM) + lane8 * 4;
            float4 v[4];
            float sum = 0.f, sq = 0.f;
            #pragma unroll
            for (int j = 0; j < 4; ++j) {
                v[j] = xr[j];
                sum += v[j].x + v[j].y + v[j].z + v[j].w;
                sq  += v[j].x * v[j].x + v[j].y * v[j].y + v[j].z * v[j].z + v[j].w * v[j].w;
            }
            #pragma unroll
            for (int o = 1; o < 8; o <<= 1) {
                sum += __shfl_xor_sync(0xffffffffu, sum, o);
                sq  += __shfl_xor_sync(0xffffffffu, sq, o);
            }
            const float mean = sum * (1.0f / 128.0f);
            const float var = sq * (1.0f / 128.0f) - mean * mean;
            const float inv = rsqrtf(var + 1e-5f);
            uint4 o0, o1;
            o0.x = pack_bf2((v[0].x - mean) * inv * gv[0].x + bv[0].x,
                            (v[0].y - mean) * inv * gv[0].y + bv[0].y);
            o0.y = pack_bf2((v[0].z - mean) * inv * gv[0].z + bv[0].z,
                            (v[0].w - mean) * inv * gv[0].w + bv[0].w);
            o0.z = pack_bf2((v[1].x - mean) * inv * gv[1].x + bv[1].x,
                            (v[1].y - mean) * inv * gv[1].y + bv[1].y);
            o0.w = pack_bf2((v[1].z - mean) * inv * gv[1].z + bv[1].z,
                            (v[1].w - mean) * inv * gv[1].w + bv[1].w);
            o1.x = pack_bf2((v[2].x - mean) * inv * gv[2].x + bv[2].x,
                            (v[2].y - mean) * inv * gv[2].y + bv[2].y);
            o1.y = pack_bf2((v[2].z - mean) * inv * gv[2].z + bv[2].z,
                            (v[2].w - mean) * inv * gv[2].w + bv[2].w);
            o1.z = pack_bf2((v[3].x - mean) * inv * gv[3].x + bv[3].x,
                            (v[3].y - mean) * inv * gv[3].y + bv[3].y);
            o1.w = pack_bf2((v[3].z - mean) * inv * gv[3].z + bv[3].z,
                            (v[3].w - mean) * inv * gv[3].w + bv[3].w);
            *(uint4*)&sX[row * SMX + lane8 * 16 + 0] = o0;
            *(uint4*)&sX[row * SMX + lane8 * 16 + 8] = o1;
        }
    }

    const int mBase = (wid & 1) * 32;
    const int nB1 = (wid >> 1) * 16;     // MMA1: warp covers 16 hidden cols
    const int nB2 = (wid >> 1) * 32;     // MMA2: warp covers 32 out cols

    const int mat = lane >> 3;
    const int aRowOff = (lane & 7) + (mat & 1) * 8;
    const int aKOff = (mat >> 1) * 8;
    const int bRowOff = (lane & 7) + ((mat >> 1) & 1) * 8;
    const int bKOff = (mat & 1) * 8;
    const int g4 = lane >> 2, t4 = lane & 3;

    float acc2[2][4][4];
    #pragma unroll
    for (int i = 0; i < 2; ++i)
        #pragma unroll
        for (int j = 0; j < 4; ++j)
            #pragma unroll
            for (int t = 0; t < 4; ++t) acc2[i][j][t] = 0.0f;

    for (int c = 0; c < 8; ++c) {
        CP_WAIT(1);          // W1(c) landed (W2(c) may fly)
        __syncthreads();

        // ---- MMA1: H[:,c*64..] (warp slice 16 cols) = sX @ W1chunk^T ----
        float hacc[2][2][4];
        #pragma unroll
        for (int i = 0; i < 2; ++i)
            #pragma unroll
            for (int j = 0; j < 2; ++j)
                #pragma unroll
                for (int t = 0; t < 4; ++t) hacc[i][j][t] = 0.0f;

        #pragma unroll
        for (int kk = 0; kk < 8; ++kk) {
            const int k0 = kk * 16;
            uint32_t a[2][4];
            #pragma unroll
            for (int mf = 0; mf < 2; ++mf) {
                uint32_t addr = uX + ((mBase + mf * 16 + aRowOff) * SMX + k0 + aKOff) * 2;
                LDSM_X4(a[mf][0], a[mf][1], a[mf][2], a[mf][3], addr);
            }
            uint32_t b0, b1x, b2, b3;
            uint32_t addr = uW1 + ((nB1 + bRowOff) * SMX + k0 + bKOff) * 2;
            LDSM_X4(b0, b1x, b2, b3, addr);
            #pragma unroll
            for (int mf = 0; mf < 2; ++mf) {
                MMA_BF16(hacc[mf][0], a[mf], b0, b1x);
                MMA_BF16(hacc[mf][1], a[mf], b2, b3);
            }
        }
        __syncthreads();   // done reading sW1

        if (c < 7) {
            #pragma unroll
            for (int it = 0; it < 4; ++it) {
                int i = tid + it * 256;
                int r = i >> 4, q = i & 15;
                cp16(uW1 + (uint32_t)(r * SMX + q * 8) * 2,
                     w1T + (size_t)(c + 1) * 8192 + (size_t)r * 128 + q * 8);
            }
            CP_COMMIT();
        }

        // GELU + bias -> sH (overlaps W1(c+1) load)
        #pragma unroll
        for (int mf = 0; mf < 2; ++mf)
            #pragma unroll
            for (int rr = 0; rr < 2; ++rr) {
                const int hrow = mBase + mf * 16 + g4 + rr * 8;
                #pragma unroll
                for (int n8 = 0; n8 < 2; ++n8) {
                    const int hcol = nB1 + n8 * 8 + 2 * t4;
                    const float2 bb = *(const float2*)&b1[c * 64 + hcol];
                    float v0 = hacc[mf][n8][rr * 2 + 0] + bb.x;
                    float v1 = hacc[mf][n8][rr * 2 + 1] + bb.y;
                    v0 = 0.5f * v0 * (1.0f + erff(v0 * 0.70710678118654752f));
                    v1 = 0.5f * v1 * (1.0f + erff(v1 * 0.70710678118654752f));
                    *(uint32_t*)&sH[hrow * SHX + hcol] = pack_bf2(v0, v1);
                }
            }
        if (c < 7) {
            CP_WAIT(1);      // W2(c) landed (W1(c+1) may fly)
        } else {
            CP_WAIT(0);      // W2(7) landed
        }
        __syncthreads();     // sH visible + sW2 ready

        // ---- MMA2: acc2 += GELU(H) @ W2chunk^T  (K = 64) ----
        #pragma unroll
        for (int kk = 0; kk < 4; ++kk) {
            const int k0 = kk * 16;
            uint32_t a[2][4];
            #pragma unroll
            for (int mf = 0; mf < 2; ++mf) {
                uint32_t addr = uH + ((mBase + mf * 16 + aRowOff) * SHX + k0 + aKOff) * 2;
                LDSM_X4(a[mf][0], a[mf][1], a[mf][2], a[mf][3], addr);
            }
            #pragma unroll
            for (int nn = 0; nn < 2; ++nn) {
                uint32_t b0, b1x, b2, b3;
                uint32_t addr = uW2 + ((nB2 + nn * 16 + bRowOff) * SHX + k0 + bKOff) * 2;
                LDSM_X4(b0, b1x, b2, b3, addr);
                #pragma unroll
                for (int mf = 0; mf < 2; ++mf) {
                    MMA_BF16(acc2[mf][nn * 2 + 0], a[mf], b0, b1x);
                    MMA_BF16(acc2[mf][nn * 2 + 1], a[mf], b2, b3);
                }
            }
        }
        __syncthreads();   // done reading sW2/sH

        if (c < 7) {
            #pragma unroll
            for (int it = 0; it < 4; ++it) {
                int i = tid + it * 256;
                int r = i >> 3, q = i & 7;
                cp16(uW2 + (uint32_t)(r * SHX + q * 8) * 2,
                     w2T + (size_t)r * 512 + (size_t)(c + 1) * 64 + q * 8);
            }
            CP_COMMIT();
        }
    }

    // ---- epilogue: + b2 + residual -> fp32 out ----
    #pragma unroll
    for (int mf = 0; mf < 2; ++mf)
        #pragma unroll
        for (int rr = 0; rr < 2; ++rr) {
            const int m = rowBase + mBase + mf * 16 + g4 + rr * 8;
            #pragma unroll
            for (int nf = 0; nf < 4; ++nf) {
                const int col = nB2 + nf * 8 + 2 * t4;
                const size_t o = (size_t)m * CDIM + col;
                const float2 bb = *(const float2*)&b2[col];
                float2 rv = *(const float2*)&X[o];
                float2 ov;
                ov.x = acc2[mf][nf][rr * 2 + 0] + bb.x + rv.x;
                ov.y = acc2[mf][nf][rr * 2 + 1] + bb.y + rv.y;
                *(float2*)&out[o] = ov;
            }
        }
}

// ---------------- host launcher ----------------
extern "C" void kernel_launch(void* const* d_in, const int* in_sizes, int n_in,
                              void* d_out, int out_size)
{
    const float* x        = (const float*)d_in[0];
    const float* norm1_g  = (const float*)d_in[1];
    const float* norm1_b  = (const float*)d_in[2];
    const float* qkv_w    = (const float*)d_in[3];
    const float* qkv_b    = (const float*)d_in[4];
    const float* rel_tab  = (const float*)d_in[5];
    const float* proj_w   = (const float*)d_in[6];
    const float* proj_b   = (const float*)d_in[7];
    const float* norm2_g  = (const float*)d_in[8];
    const float* norm2_b  = (const float*)d_in[9];
    const float* fc1_w    = (const float*)d_in[10];
    const float* fc1_b    = (const float*)d_in[11];
    const float* fc2_w    = (const float*)d_in[12];
    const float* fc2_b    = (const float*)d_in[13];
    float* out = (float*)d_out;

    __nv_bfloat16 *attnb, *wT;
    float* x1;
    cudaGetSymbolAddress((void**)&attnb, g_attnb);
    cudaGetSymbolAddress((void**)&wT,    g_wT);
    cudaGetSymbolAddress((void**)&x1,    g_x1);

    const int M = M_TOK;

    cudaFuncSetAttribute(attn_fused, cudaFuncAttributeMaxDynamicSharedMemorySize, ATTF_SMEM);
    cudaFuncSetAttribute(mlp_fused, cudaFuncAttributeMaxDynamicSharedMemorySize, MLP_SMEM);

    // 0) weights -> bf16 [N,K]
    convert_w_kernel<<<WT_TOTAL / 256, 256>>>(qkv_w, proj_w, fc1_w, fc2_w, wT);

    // 1) fused LN1 + window gather + QKV + attention -> bf16 attnb
    attn_fused<<<M / NTOK, 256, ATTF_SMEM>>>(x, wT + WQ_OFF, norm1_g, norm1_b,
                                             qkv_b, rel_tab, attnb);

    // 2) proj GEMM + reverse/unshift + residual -> fp32 x1
    gemm_proj<<<dim3(1, M / 128), 256>>>(attnb, wT + WP_OFF, proj_b, x, x1, M, 128, 128);

    // 3) fused MLP: LN2 + FC1 + GELU + FC2 + residual -> fp32 out
    mlp_fused<<<M / 64, 256, MLP_SMEM>>>(x1, wT + W1_OFF, wT + W2_OFF,
                                         norm2_g, norm2_b, fc1_b, fc2_b, out);
}

// round 15
// speedup vs baseline: 1.0320x; 1.0320x over previous
#include <cuda_runtime.h>
#include <cuda_bf16.h>
#include <math.h>
#include <stdint.h>

// ---------------- problem constants ----------------
#define BATCH 64
#define HH 56
#define WW_ 56
#define CDIM 128
#define L_TOK (HH * WW_)            // 3136
#define M_TOK (BATCH * L_TOK)       // 200704
#define NHEAD 4
#define HDIM 32
#define WS 7
#define NWIN_SIDE 8
#define NTOK 49
#define SHIFT 3
#define HIDDEN 512

// weight-transpose buffer offsets (bf16 [N,K] layouts)
#define WQ_OFF 0            // 384*128
#define WP_OFF 49152        // 128*128
#define W1_OFF 65536        // 512*128
#define W2_OFF 131072       // 128*512
#define WT_TOTAL 196608

// ---------------- scratch ----------------
__device__ __nv_bfloat16 g_attnb[(size_t)M_TOK * CDIM];
__device__ float g_x1[(size_t)M_TOK * CDIM];
__device__ __nv_bfloat16 g_wT[WT_TOTAL];

__device__ __forceinline__ uint32_t smem_u32(const void* p) {
    uint32_t a;
    asm("{ .reg .u64 t; cvta.to.shared.u64 t, %1; cvt.u32.u64 %0, t; }" : "=r"(a) : "l"(p));
    return a;
}
__device__ __forceinline__ uint32_t pack_bf2(float a, float b) {
    __nv_bfloat162 t = __floats2bfloat162_rn(a, b);
    return *reinterpret_cast<uint32_t*>(&t);
}
__device__ __forceinline__ void cp16(uint32_t dst, const void* src) {
    asm volatile("cp.async.cg.shared.global [%0], [%1], 16;" :: "r"(dst), "l"(src));
}
#define CP_COMMIT() asm volatile("cp.async.commit_group;" ::: "memory")
#define CP_WAIT(N)  asm volatile("cp.async.wait_group %0;" :: "n"(N) : "memory")

#define LDSM_X4(r0, r1, r2, r3, addr) \
    asm volatile("ldmatrix.sync.aligned.m8n8.x4.shared.b16 {%0,%1,%2,%3}, [%4];" \
        : "=r"(r0), "=r"(r1), "=r"(r2), "=r"(r3) : "r"(addr))

#define MMA_BF16(c, a, b0, b1) \
    asm volatile("mma.sync.aligned.m16n8k16.row.col.f32.bf16.bf16.f32 " \
        "{%0,%1,%2,%3}, {%4,%5,%6,%7}, {%8,%9}, {%0,%1,%2,%3};" \
        : "+f"((c)[0]), "+f"((c)[1]), "+f"((c)[2]), "+f"((c)[3]) \
        : "r"((a)[0]), "r"((a)[1]), "r"((a)[2]), "r"((a)[3]), "r"(b0), "r"(b1))

// ---------------- weight transpose + bf16 convert ----------------
__global__ void __launch_bounds__(256) convert_w_kernel(
    const float* __restrict__ qkv_w, const float* __restrict__ proj_w,
    const float* __restrict__ fc1_w, const float* __restrict__ fc2_w,
    __nv_bfloat16* __restrict__ wT)
{
    int i = blockIdx.x * 256 + threadIdx.x;
    if (i < WQ_OFF + 49152) {
        int j = i - WQ_OFF; int n = j / 128, k = j % 128;
        wT[i] = __float2bfloat16(qkv_w[k * 384 + n]);
    } else if (i < WP_OFF + 16384) {
        int j = i - WP_OFF; int n = j / 128, k = j % 128;
        wT[i] = __float2bfloat16(proj_w[k * 128 + n]);
    } else if (i < W1_OFF + 65536) {
        int j = i - W1_OFF; int n = j / 128, k = j % 128;
        wT[i] = __float2bfloat16(fc1_w[k * 512 + n]);
    } else if (i < W2_OFF + 65536) {
        int j = i - W2_OFF; int n = j / 512, k = j % 512;
        wT[i] = __float2bfloat16(fc2_w[k * 128 + n]);
    }
}

// =========================================================================
// Fused front half: LN1(+shift+gather) + QKV + attention. (R13, best)
// =========================================================================
#define AS 136
#define SVT 72
#define SPP 72
#define UNI_ELEM 18432
#define ATTF_BASE (64*AS*2 + 36864 + 64*AS*2 + 64*AS*2 + 128*SVT*2)
#define ATTF_SMEM (ATTF_BASE + 192 + 2704)

__global__ void __launch_bounds__(256) attn_fused(
    const float* __restrict__ X, const __nv_bfloat16* __restrict__ wq,
    const float* __restrict__ lng, const float* __restrict__ lnb,
    const float* __restrict__ qkvbias, const float* __restrict__ bias_table,
    __nv_bfloat16* __restrict__ out)
{
    extern __shared__ __align__(16) char dsm[];
    __nv_bfloat16* sX  = (__nv_bfloat16*)dsm;
    __nv_bfloat16* uni = sX + 64 * AS;
    __nv_bfloat16* sW  = uni;
    __nv_bfloat16* sP  = uni;
    __nv_bfloat16* sQ  = uni + UNI_ELEM;
    __nv_bfloat16* sK  = sQ + 64 * AS;
    __nv_bfloat16* sVt = sK + 64 * AS;
    unsigned char* sGrp = (unsigned char*)(dsm + ATTF_BASE);
    signed char*   sDiv = (signed char*)(sGrp + 64);
    signed char*   sMod = (signed char*)(sDiv + 64);
    float*         sBias = (float*)(dsm + ATTF_BASE + 192);

    const int tid = threadIdx.x, wid = tid >> 5, lane = tid & 31;
    const int win = blockIdx.x;
    const int wloc = win & 63, wh = wloc >> 3, wwi = wloc & 7;

    const int mat = lane >> 3;
    const int aRowOff = (lane & 7) + (mat & 1) * 8;
    const int aKOff = (mat >> 1) * 8;
    const int bRowOff = (lane & 7) + ((mat >> 1) & 1) * 8;
    const int bKOff = (mat & 1) * 8;
    const int g4 = lane >> 2, t4 = lane & 3;

    const uint32_t uX = smem_u32(sX), uW = smem_u32(sW);
    const uint32_t uQ = smem_u32(sQ), uK = smem_u32(sK), uVt = smem_u32(sVt);

    {
        #pragma unroll
        for (int it = 0; it < 8; ++it) {
            int i = tid + it * 256;
            int r = i >> 4, qq = i & 15;
            cp16(uW + (uint32_t)(r * AS + qq * 8) * 2, wq + (size_t)r * 128 + qq * 8);
        }
        CP_COMMIT();
    }

    for (int i = tid; i < 676; i += 256) sBias[i] = bias_table[i];

    {
        const int row8 = tid >> 3;
        const int lane8 = tid & 7;
        const float4 gv[4] = {
            *(const float4*)&lng[lane8 * 16 + 0],  *(const float4*)&lng[lane8 * 16 + 4],
            *(const float4*)&lng[lane8 * 16 + 8],  *(const float4*)&lng[lane8 * 16 + 12] };
        const float4 bv[4] = {
            *(const float4*)&lnb[lane8 * 16 + 0],  *(const float4*)&lnb[lane8 * 16 + 4],
            *(const float4*)&lnb[lane8 * 16 + 8],  *(const float4*)&lnb[lane8 * 16 + 12] };
        #pragma unroll
        for (int pass = 0; pass < 2; ++pass) {
            const int row = pass * 32 + row8;
            const int trow = (row < NTOK) ? row : (NTOK - 1);
            const int ih = trow / WS, iw = trow - ih * WS;
            int h = wh * WS + ih + SHIFT; if (h >= HH) h -= HH;
            int w = wwi * WS + iw + SHIFT; if (w >= WW_) w -= WW_;
            const int srow = (win >> 6) * L_TOK + h * WW_ + w;
            const float4* xr = (const float4*)(X + (size_t)srow * CDIM) + lane8 * 4;
            float4 v[4];
            float sum = 0.f, sq = 0.f;
            #pragma unroll
            for (int j = 0; j < 4; ++j) {
                v[j] = xr[j];
                sum += v[j].x + v[j].y + v[j].z + v[j].w;
                sq  += v[j].x * v[j].x + v[j].y * v[j].y + v[j].z * v[j].z + v[j].w * v[j].w;
            }
            #pragma unroll
            for (int o = 1; o < 8; o <<= 1) {
                sum += __shfl_xor_sync(0xffffffffu, sum, o);
                sq  += __shfl_xor_sync(0xffffffffu, sq, o);
            }
            const float mean = sum * (1.0f / 128.0f);
            const float var = sq * (1.0f / 128.0f) - mean * mean;
            const float inv = rsqrtf(var + 1e-5f);
            uint4 o0, o1;
            o0.x = pack_bf2((v[0].x - mean) * inv * gv[0].x + bv[0].x,
                            (v[0].y - mean) * inv * gv[0].y + bv[0].y);
            o0.y = pack_bf2((v[0].z - mean) * inv * gv[0].z + bv[0].z,
                            (v[0].w - mean) * inv * gv[0].w + bv[0].w);
            o0.z = pack_bf2((v[1].x - mean) * inv * gv[1].x + bv[1].x,
                            (v[1].y - mean) * inv * gv[1].y + bv[1].y);
            o0.w = pack_bf2((v[1].z - mean) * inv * gv[1].z + bv[1].z,
                            (v[1].w - mean) * inv * gv[1].w + bv[1].w);
            o1.x = pack_bf2((v[2].x - mean) * inv * gv[2].x + bv[2].x,
                            (v[2].y - mean) * inv * gv[2].y + bv[2].y);
            o1.y = pack_bf2((v[2].z - mean) * inv * gv[2].z + bv[2].z,
                            (v[2].w - mean) * inv * gv[2].w + bv[2].w);
            o1.z = pack_bf2((v[3].x - mean) * inv * gv[3].x + bv[3].x,
                            (v[3].y - mean) * inv * gv[3].y + bv[3].y);
            o1.w = pack_bf2((v[3].z - mean) * inv * gv[3].z + bv[3].z,
                            (v[3].w - mean) * inv * gv[3].w + bv[3].w);
            *(uint4*)&sX[row * AS + lane8 * 16 + 0] = o0;
            *(uint4*)&sX[row * AS + lane8 * 16 + 8] = o1;
        }
    }
    if (tid < 64) {
        int ih = tid / 7, iw = tid % 7;
        sDiv[tid] = (signed char)ih;
        sMod[tid] = (signed char)iw;
        int hs = wh * WS + ih, ws = wwi * WS + iw;
        int gh = hs < (HH - WS) ? 0 : (hs < (HH - SHIFT) ? 1 : 2);
        int gw = ws < (WW_ - WS) ? 0 : (ws < (WW_ - SHIFT) ? 1 : 2);
        sGrp[tid] = (unsigned char)(gh * 3 + gw);
    }

    const int mBq = (wid & 1) * 32;
    const int nBq = (wid >> 1) * 32;
    const float scale = 0.17677669529663689f;

    for (int p = 0; p < 3; ++p) {
        CP_WAIT(0);
        __syncthreads();

        float qa[2][4][4];
        #pragma unroll
        for (int i = 0; i < 2; ++i)
            #pragma unroll
            for (int j = 0; j < 4; ++j)
                #pragma unroll
                for (int t = 0; t < 4; ++t) qa[i][j][t] = 0.0f;

        #pragma unroll
        for (int kk = 0; kk < 8; ++kk) {
            const int k0 = kk * 16;
            uint32_t a[2][4];
            #pragma unroll
            for (int mf = 0; mf < 2; ++mf) {
                uint32_t addr = uX + ((mBq + mf * 16 + aRowOff) * AS + k0 + aKOff) * 2;
                LDSM_X4(a[mf][0], a[mf][1], a[mf][2], a[mf][3], addr);
            }
            #pragma unroll
            for (int nn = 0; nn < 2; ++nn) {
                uint32_t b0, b1, b2, b3;
                uint32_t addr = uW + ((nBq + nn * 16 + bRowOff) * AS + k0 + bKOff) * 2;
                LDSM_X4(b0, b1, b2, b3, addr);
                #pragma unroll
                for (int mf = 0; mf < 2; ++mf) {
                    MMA_BF16(qa[mf][nn * 2 + 0], a[mf], b0, b1);
                    MMA_BF16(qa[mf][nn * 2 + 1], a[mf], b2, b3);
                }
            }
        }
        __syncthreads();

        if (p < 2) {
            #pragma unroll
            for (int it = 0; it < 8; ++it) {
                int i = tid + it * 256;
                int r = i >> 4, qq = i & 15;
                cp16(uW + (uint32_t)(r * AS + qq * 8) * 2,
                     wq + (size_t)(p + 1) * 16384 + (size_t)r * 128 + qq * 8);
            }
            CP_COMMIT();
        }

        #pragma unroll
        for (int mf = 0; mf < 2; ++mf)
            #pragma unroll
            for (int rr = 0; rr < 2; ++rr) {
                const int m = mBq + mf * 16 + g4 + rr * 8;
                #pragma unroll
                for (int nf = 0; nf < 4; ++nf) {
                    const int n = nBq + nf * 8 + 2 * t4;
                    const float2 bf2 = *(const float2*)&qkvbias[p * 128 + n];
                    float v0 = qa[mf][nf][rr * 2 + 0] + bf2.x;
                    float v1 = qa[mf][nf][rr * 2 + 1] + bf2.y;
                    if (p == 0) {
                        *(uint32_t*)&sQ[m * AS + n] = pack_bf2(v0 * scale, v1 * scale);
                    } else if (p == 1) {
                        *(uint32_t*)&sK[m * AS + n] = pack_bf2(v0, v1);
                    } else {
                        sVt[n * SVT + m]       = __float2bfloat16(v0);
                        sVt[(n + 1) * SVT + m] = __float2bfloat16(v1);
                    }
                }
            }
    }
    __syncthreads();

    const int h = wid >> 1;
    const int mBase = (wid & 1) * 32;
    const int colQ = h * 32;
    __nv_bfloat16* sPw = sP + wid * 32 * SPP;
    const uint32_t uP = smem_u32(sPw);

    float acc[2][8][4];
    #pragma unroll
    for (int i = 0; i < 2; ++i)
        #pragma unroll
        for (int j = 0; j < 8; ++j)
            #pragma unroll
            for (int t = 0; t < 4; ++t) acc[i][j][t] = 0.0f;

    uint32_t a[2][2][4];
    #pragma unroll
    for (int mf = 0; mf < 2; ++mf)
        #pragma unroll
        for (int ks = 0; ks < 2; ++ks) {
            uint32_t addr = uQ + ((mBase + mf * 16 + aRowOff) * AS + colQ + ks * 16 + aKOff) * 2;
            LDSM_X4(a[mf][ks][0], a[mf][ks][1], a[mf][ks][2], a[mf][ks][3], addr);
        }
    #pragma unroll
    for (int nb = 0; nb < 4; ++nb) {
        uint32_t b[2][4];
        #pragma unroll
        for (int ks = 0; ks < 2; ++ks) {
            uint32_t addr = uK + ((nb * 16 + bRowOff) * AS + colQ + ks * 16 + bKOff) * 2;
            LDSM_X4(b[ks][0], b[ks][1], b[ks][2], b[ks][3], addr);
        }
        #pragma unroll
        for (int ks = 0; ks < 2; ++ks)
            #pragma unroll
            for (int mf = 0; mf < 2; ++mf) {
                MMA_BF16(acc[mf][nb * 2 + 0], a[mf][ks], b[ks][0], b[ks][1]);
                MMA_BF16(acc[mf][nb * 2 + 1], a[mf][ks], b[ks][2], b[ks][3]);
            }
    }

    int ii[2][2];
    #pragma unroll
    for (int mf = 0; mf < 2; ++mf)
        #pragma unroll
        for (int rr = 0; rr < 2; ++rr) ii[mf][rr] = mBase + mf * 16 + g4 + rr * 8;

    float mx[2][2] = {{-1e30f, -1e30f}, {-1e30f, -1e30f}};
    #pragma unroll
    for (int mf = 0; mf < 2; ++mf)
        #pragma unroll
        for (int nf = 0; nf < 8; ++nf)
            #pragma unroll
            for (int e = 0; e < 4; ++e) {
                int rr = e >> 1;
                int jj = nf * 8 + 2 * t4 + (e & 1);
                float s;
                if (jj < NTOK) {
                    int i0 = ii[mf][rr];
                    int i0c = (i0 < NTOK) ? i0 : (NTOK - 1);
                    int dh = sDiv[i0c] - sDiv[jj] + 6;
                    int dw = sMod[i0c] - sMod[jj] + 6;
                    float bv = sBias[(dh * 13 + dw) * NHEAD + h];
                    float mk = (sGrp[i0c] != sGrp[jj]) ? -100.0f : 0.0f;
                    s = acc[mf][nf][e] + bv + mk;
                } else {
                    s = -1e30f;
                }
                acc[mf][nf][e] = s;
                mx[mf][rr] = fmaxf(mx[mf][rr], s);
            }
    #pragma unroll
    for (int mf = 0; mf < 2; ++mf)
        #pragma unroll
        for (int rr = 0; rr < 2; ++rr) {
            float m = mx[mf][rr];
            m = fmaxf(m, __shfl_xor_sync(0xffffffffu, m, 1));
            m = fmaxf(m, __shfl_xor_sync(0xffffffffu, m, 2));
            mx[mf][rr] = m;
        }

    float sm[2][2] = {{0.f, 0.f}, {0.f, 0.f}};
    #pragma unroll
    for (int mf = 0; mf < 2; ++mf)
        #pragma unroll
        for (int nf = 0; nf < 8; ++nf)
            #pragma unroll
            for (int e = 0; e < 4; ++e) {
                int rr = e >> 1;
                float ev = __expf(acc[mf][nf][e] - mx[mf][rr]);
                acc[mf][nf][e] = ev;
                sm[mf][rr] += ev;
            }
    #pragma unroll
    for (int mf = 0; mf < 2; ++mf)
        #pragma unroll
        for (int rr = 0; rr < 2; ++rr) {
            float s = sm[mf][rr];
            s += __shfl_xor_sync(0xffffffffu, s, 1);
            s += __shfl_xor_sync(0xffffffffu, s, 2);
            sm[mf][rr] = s;
        }

    #pragma unroll
    for (int mf = 0; mf < 2; ++mf)
        #pragma unroll
        for (int rr = 0; rr < 2; ++rr) {
            int prow = mf * 16 + g4 + rr * 8;
            #pragma unroll
            for (int nf = 0; nf < 8; ++nf) {
                uint32_t u = pack_bf2(acc[mf][nf][rr * 2], acc[mf][nf][rr * 2 + 1]);
                *(uint32_t*)&sPw[prow * SPP + nf * 8 + 2 * t4] = u;
            }
        }
    __syncwarp();

    float acc2[2][4][4];
    #pragma unroll
    for (int i = 0; i < 2; ++i)
        #pragma unroll
        for (int j = 0; j < 4; ++j)
            #pragma unroll
            for (int t = 0; t < 4; ++t) acc2[i][j][t] = 0.0f;

    #pragma unroll
    for (int kc = 0; kc < 4; ++kc) {
        uint32_t a2[2][4], b2[2][4];
        #pragma unroll
        for (int mf = 0; mf < 2; ++mf) {
            uint32_t addr = uP + ((mf * 16 + aRowOff) * SPP + kc * 16 + aKOff) * 2;
            LDSM_X4(a2[mf][0], a2[mf][1], a2[mf][2], a2[mf][3], addr);
        }
        #pragma unroll
        for (int nb = 0; nb < 2; ++nb) {
            uint32_t addr = uVt + ((colQ + nb * 16 + bRowOff) * SVT + kc * 16 + bKOff) * 2;
            LDSM_X4(b2[nb][0], b2[nb][1], b2[nb][2], b2[nb][3], addr);
        }
        #pragma unroll
        for (int mf = 0; mf < 2; ++mf)
            #pragma unroll
            for (int nb = 0; nb < 2; ++nb) {
                MMA_BF16(acc2[mf][nb * 2 + 0], a2[mf], b2[nb][0], b2[nb][1]);
                MMA_BF16(acc2[mf][nb * 2 + 1], a2[mf], b2[nb][2], b2[nb][3]);
            }
    }

    #pragma unroll
    for (int mf = 0; mf < 2; ++mf)
        #pragma unroll
        for (int rr = 0; rr < 2; ++rr) {
            int i0 = ii[mf][rr];
            if (i0 < NTOK) {
                float inv = 1.0f / sm[mf][rr];
                __nv_bfloat16* orow = out + ((size_t)win * NTOK + i0) * CDIM + colQ;
                #pragma unroll
                for (int nf = 0; nf < 4; ++nf) {
                    float v0 = acc2[mf][nf][rr * 2 + 0] * inv;
                    float v1 = acc2[mf][nf][rr * 2 + 1] * inv;
                    *(uint32_t*)&orow[nf * 8 + 2 * t4] = pack_bf2(v0, v1);
                }
            }
        }
}

// =========================================================================
// proj GEMM: K=128 resident, cp.async fill, single sync, 8 k-steps.
// EPI: +bias +res, permuted row -> f32 [prow*128]
// =========================================================================
#define SPA 136
#define PROJ_SMEM (2 * 128 * SPA * 2)   // 69,632 B

__global__ void __launch_bounds__(256) gemm_proj(
    const __nv_bfloat16* __restrict__ A, const __nv_bfloat16* __restrict__ Bt,
    const float* __restrict__ bias, const float* __restrict__ res,
    float* __restrict__ C, int M, int N, int K)
{
    extern __shared__ __align__(16) char dsm[];
    __nv_bfloat16* sA = (__nv_bfloat16*)dsm;       // [128][SPA]
    __nv_bfloat16* sB = sA + 128 * SPA;            // [128][SPA]

    const int tid = threadIdx.x;
    const int wid = tid >> 5, lane = tid & 31;
    const int rowBase = blockIdx.y << 7;

    const int mBase = (wid & 3) * 32;
    const int nBase = (wid >> 2) * 64;

    const uint32_t uA = smem_u32(sA), uB = smem_u32(sB);
    const int mat = lane >> 3;
    const int aRowOff = (lane & 7) + (mat & 1) * 8;
    const int aKOff = (mat >> 1) * 8;
    const int bRowOff = (lane & 7) + ((mat >> 1) & 1) * 8;
    const int bKOff = (mat & 1) * 8;

    // async fill: A tile (128x128 bf16) + B (128x128 bf16)
    {
        const __nv_bfloat16* Ag = A + (size_t)rowBase * CDIM;
        #pragma unroll
        for (int it = 0; it < 8; ++it) {
            int i = tid + it * 256;
            int r = i >> 4, q = i & 15;
            cp16(uA + (uint32_t)(r * SPA + q * 8) * 2, Ag + (size_t)r * CDIM + q * 8);
        }
        #pragma unroll
        for (int it = 0; it < 8; ++it) {
            int i = tid + it * 256;
            int r = i >> 4, q = i & 15;
            cp16(uB + (uint32_t)(r * SPA + q * 8) * 2, Bt + (size_t)r * CDIM + q * 8);
        }
        CP_COMMIT();
    }

    float acc[2][8][4];
    #pragma unroll
    for (int i = 0; i < 2; ++i)
        #pragma unroll
        for (int j = 0; j < 8; ++j)
            #pragma unroll
            for (int t = 0; t < 4; ++t) acc[i][j][t] = 0.0f;

    CP_WAIT(0);
    __syncthreads();

    #pragma unroll
    for (int kk = 0; kk < 8; ++kk) {
        const int k0 = kk * 16;
        uint32_t a[2][4];
        #pragma unroll
        for (int mf = 0; mf < 2; ++mf) {
            uint32_t addr = uA + ((mBase + mf * 16 + aRowOff) * SPA + k0 + aKOff) * 2;
            LDSM_X4(a[mf][0], a[mf][1], a[mf][2], a[mf][3], addr);
        }
        #pragma unroll
        for (int nn = 0; nn < 4; ++nn) {
            uint32_t b0, b1, b2, b3;
            uint32_t addr = uB + ((nBase + nn * 16 + bRowOff) * SPA + k0 + bKOff) * 2;
            LDSM_X4(b0, b1, b2, b3, addr);
            #pragma unroll
            for (int mf = 0; mf < 2; ++mf) {
                MMA_BF16(acc[mf][nn * 2 + 0], a[mf], b0, b1);
                MMA_BF16(acc[mf][nn * 2 + 1], a[mf], b2, b3);
            }
        }
    }

    const int g4 = lane >> 2, t4 = lane & 3;
    #pragma unroll
    for (int mf = 0; mf < 2; ++mf)
        #pragma unroll
        for (int rr = 0; rr < 2; ++rr) {
            const int m = rowBase + mBase + mf * 16 + g4 + rr * 8;
            int win = m / NTOK, tt = m - win * NTOK;
            int bimg = win >> 6, wloc = win & 63;
            int wh = wloc >> 3, wwi = wloc & 7;
            int ih = tt / WS, iw = tt - ih * WS;
            int h = wh * WS + ih + SHIFT; if (h >= HH) h -= HH;
            int w = wwi * WS + iw + SHIFT; if (w >= WW_) w -= WW_;
            const int prow = bimg * L_TOK + h * WW_ + w;
            #pragma unroll
            for (int nf = 0; nf < 8; ++nf) {
                const int col = nBase + nf * 8 + 2 * t4;
                const float2 bf2 = *(const float2*)&bias[col];
                float v0 = acc[mf][nf][rr * 2 + 0] + bf2.x;
                float v1 = acc[mf][nf][rr * 2 + 1] + bf2.y;
                const size_t o = (size_t)prow * CDIM + col;
                float2 rv = *(const float2*)&res[o];
                float2 ov; ov.x = v0 + rv.x; ov.y = v1 + rv.y;
                *(float2*)&C[o] = ov;
            }
        }
}

// =========================================================================
// Fused MLP: LN2 + FC1 + GELU + FC2 + residual, cp.async pipelined. (R13)
// =========================================================================
#define SMX 136
#define MLP_SMEM ((64 + 64 + 128 + 128) * SMX * 2)

__global__ void __launch_bounds__(256) mlp_fused(
    const float* __restrict__ X, const __nv_bfloat16* __restrict__ w1T,
    const __nv_bfloat16* __restrict__ w2T,
    const float* __restrict__ lng, const float* __restrict__ lnb,
    const float* __restrict__ b1, const float* __restrict__ b2,
    float* __restrict__ out)
{
    extern __shared__ __align__(16) char dsm[];
    __nv_bfloat16* sX  = (__nv_bfloat16*)dsm;
    __nv_bfloat16* sH  = sX + 64 * SMX;
    __nv_bfloat16* sW1 = sH + 64 * SMX;
    __nv_bfloat16* sW2 = sW1 + 128 * SMX;

    const int tid = threadIdx.x;
    const int wid = tid >> 5, lane = tid & 31;
    const int rowBase = blockIdx.x << 6;

    const uint32_t uX = smem_u32(sX), uH = smem_u32(sH);
    const uint32_t uW1 = smem_u32(sW1), uW2 = smem_u32(sW2);

    {
        #pragma unroll
        for (int it = 0; it < 8; ++it) {
            int i = tid + it * 256;
            int r = i >> 4, q = i & 15;
            cp16(uW1 + (uint32_t)(r * SMX + q * 8) * 2, w1T + (size_t)r * 128 + q * 8);
        }
        CP_COMMIT();
        #pragma unroll
        for (int it = 0; it < 8; ++it) {
            int i = tid + it * 256;
            int r = i >> 4, q = i & 15;
            cp16(uW2 + (uint32_t)(r * SMX + q * 8) * 2, w2T + (size_t)r * 512 + q * 8);
        }
        CP_COMMIT();
    }

    // ---- LN2 on 64 token rows ----
    {
        const int row8 = tid >> 3;
        const int lane8 = tid & 7;
        const float4 gv[4] = {
            *(const float4*)&lng[lane8 * 16 + 0],  *(const float4*)&lng[lane8 * 16 + 4],
            *(const float4*)&lng[lane8 * 16 + 8],  *(const float4*)&lng[lane8 * 16 + 12] };
        const float4 bv[4] = {
            *(const float4*)&lnb[lane8 * 16 + 0],  *(const float4*)&lnb[lane8 * 16 + 4],
            *(const float4*)&lnb[lane8 * 16 + 8],  *(const float4*)&lnb[lane8 * 16 + 12] };
        #pragma unroll
        for (int pass = 0; pass < 2; ++pass) {
            const int row = pass * 32 + row8;
            const float4* xr = (const float4*)(X + (size_t)(rowBase + row) * CDIM) + lane8 * 4;
            float4 v[4];
            float sum = 0.f, sq = 0.f;
            #pragma unroll
            for (int j = 0; j < 4; ++j) {
                v[j] = xr[j];
                sum += v[j].x + v[j].y + v[j].z + v[j].w;
                sq  += v[j].x * v[j].x + v[j].y * v[j].y + v[j].z * v[j].z + v[j].w * v[j].w;
            }
            #pragma unroll
            for (int o = 1; o < 8; o <<= 1) {
                sum += __shfl_xor_sync(0xffffffffu, sum, o);
                sq  += __shfl_xor_sync(0xffffffffu, sq, o);
            }
            const float mean = sum * (1.0f / 128.0f);
            const float var = sq * (1.0f / 128.0f) - mean * mean;
            const float inv = rsqrtf(var + 1e-5f);
            uint4 o0, o1;
            o0.x = pack_bf2((v[0].x - mean) * inv * gv[0].x + bv[0].x,
                            (v[0].y - mean) * inv * gv[0].y + bv[0].y);
            o0.y = pack_bf2((v[0].z - mean) * inv * gv[0].z + bv[0].z,
                            (v[0].w - mean) * inv * gv[0].w + bv[0].w);
            o0.z = pack_bf2((v[1].x - mean) * inv * gv[1].x + bv[1].x,
                            (v[1].y - mean) * inv * gv[1].y + bv[1].y);
            o0.w = pack_bf2((v[1].z - mean) * inv * gv[1].z + bv[1].z,
                            (v[1].w - mean) * inv * gv[1].w + bv[1].w);
            o1.x = pack_bf2((v[2].x - mean) * inv * gv[2].x + bv[2].x,
                            (v[2].y - mean) * inv * gv[2].y + bv[2].y);
            o1.y = pack_bf2((v[2].z - mean) * inv * gv[2].z + bv[2].z,
                            (v[2].w - mean) * inv * gv[2].w + bv[2].w);
            o1.z = pack_bf2((v[3].x - mean) * inv * gv[3].x + bv[3].x,
                            (v[3].y - mean) * inv * gv[3].y + bv[3].y);
            o1.w = pack_bf2((v[3].z - mean) * inv * gv[3].z + bv[3].z,
                            (v[3].w - mean) * inv * gv[3].w + bv[3].w);
            *(uint4*)&sX[row * SMX + lane8 * 16 + 0] = o0;
            *(uint4*)&sX[row * SMX + lane8 * 16 + 8] = o1;
        }
    }

    const int mBase = (wid & 1) * 32;
    const int nBase = (wid >> 1) * 32;

    const int mat = lane >> 3;
    const int aRowOff = (lane & 7) + (mat & 1) * 8;
    const int aKOff = (mat >> 1) * 8;
    const int bRowOff = (lane & 7) + ((mat >> 1) & 1) * 8;
    const int bKOff = (mat & 1) * 8;
    const int g4 = lane >> 2, t4 = lane & 3;

    float acc2[2][4][4];
    #pragma unroll
    for (int i = 0; i < 2; ++i)
        #pragma unroll
        for (int j = 0; j < 4; ++j)
            #pragma unroll
            for (int t = 0; t < 4; ++t) acc2[i][j][t] = 0.0f;

    for (int c = 0; c < 4; ++c) {
        CP_WAIT(1);
        __syncthreads();

        float hacc[2][4][4];
        #pragma unroll
        for (int i = 0; i < 2; ++i)
            #pragma unroll
            for (int j = 0; j < 4; ++j)
                #pragma unroll
                for (int t = 0; t < 4; ++t) hacc[i][j][t] = 0.0f;

        #pragma unroll
        for (int kk = 0; kk < 8; ++kk) {
            const int k0 = kk * 16;
            uint32_t a[2][4];
            #pragma unroll
            for (int mf = 0; mf < 2; ++mf) {
                uint32_t addr = uX + ((mBase + mf * 16 + aRowOff) * SMX + k0 + aKOff) * 2;
                LDSM_X4(a[mf][0], a[mf][1], a[mf][2], a[mf][3], addr);
            }
            #pragma unroll
            for (int nn = 0; nn < 2; ++nn) {
                uint32_t b0, b1, b2, b3;
                uint32_t addr = uW1 + ((nBase + nn * 16 + bRowOff) * SMX + k0 + bKOff) * 2;
                LDSM_X4(b0, b1, b2, b3, addr);
                #pragma unroll
                for (int mf = 0; mf < 2; ++mf) {
                    MMA_BF16(hacc[mf][nn * 2 + 0], a[mf], b0, b1);
                    MMA_BF16(hacc[mf][nn * 2 + 1], a[mf], b2, b3);
                }
            }
        }
        __syncthreads();

        if (c < 3) {
            #pragma unroll
            for (int it = 0; it < 8; ++it) {
                int i = tid + it * 256;
                int r = i >> 4, q = i & 15;
                cp16(uW1 + (uint32_t)(r * SMX + q * 8) * 2,
                     w1T + (size_t)(c + 1) * 16384 + (size_t)r * 128 + q * 8);
            }
            CP_COMMIT();
        }

        #pragma unroll
        for (int mf = 0; mf < 2; ++mf)
            #pragma unroll
            for (int rr = 0; rr < 2; ++rr) {
                const int hrow = mBase + mf * 16 + g4 + rr * 8;
                #pragma unroll
                for (int nf = 0; nf < 4; ++nf) {
                    const int hcol = nBase + nf * 8 + 2 * t4;
                    const float2 bb = *(const float2*)&b1[c * 128 + hcol];
                    float v0 = hacc[mf][nf][rr * 2 + 0] + bb.x;
                    float v1 = hacc[mf][nf][rr * 2 + 1] + bb.y;
                    v0 = 0.5f * v0 * (1.0f + erff(v0 * 0.70710678118654752f));
                    v1 = 0.5f * v1 * (1.0f + erff(v1 * 0.70710678118654752f));
                    *(uint32_t*)&sH[hrow * SMX + hcol] = pack_bf2(v0, v1);
                }
            }
        if (c < 3) {
            CP_WAIT(1);
        } else {
            CP_WAIT(0);
        }
        __syncthreads();

        #pragma unroll
        for (int kk = 0; kk < 8; ++kk) {
            const int k0 = kk * 16;
            uint32_t a[2][4];
            #pragma unroll
            for (int mf = 0; mf < 2; ++mf) {
                uint32_t addr = uH + ((mBase + mf * 16 + aRowOff) * SMX + k0 + aKOff) * 2;
                LDSM_X4(a[mf][0], a[mf][1], a[mf][2], a[mf][3], addr);
            }
            #pragma unroll
            for (int nn = 0; nn < 2; ++nn) {
                uint32_t b0, b1, b2, b3;
                uint32_t addr = uW2 + ((nBase + nn * 16 + bRowOff) * SMX + k0 + bKOff) * 2;
                LDSM_X4(b0, b1, b2, b3, addr);
                #pragma unroll
                for (int mf = 0; mf < 2; ++mf) {
                    MMA_BF16(acc2[mf][nn * 2 + 0], a[mf], b0, b1);
                    MMA_BF16(acc2[mf][nn * 2 + 1], a[mf], b2, b3);
                }
            }
        }
        __syncthreads();

        if (c < 3) {
            #pragma unroll
            for (int it = 0; it < 8; ++it) {
                int i = tid + it * 256;
                int r = i >> 4, q = i & 15;
                cp16(uW2 + (uint32_t)(r * SMX + q * 8) * 2,
                     w2T + (size_t)r * 512 + (size_t)(c + 1) * 128 + q * 8);
            }
            CP_COMMIT();
        }
    }

    #pragma unroll
    for (int mf = 0; mf < 2; ++mf)
        #pragma unroll
        for (int rr = 0; rr < 2; ++rr) {
            const int m = rowBase + mBase + mf * 16 + g4 + rr * 8;
            #pragma unroll
            for (int nf = 0; nf < 4; ++nf) {
                const int col = nBase + nf * 8 + 2 * t4;
                const size_t o = (size_t)m * CDIM + col;
                const float2 bb = *(const float2*)&b2[col];
                float2 rv = *(const float2*)&X[o];
                float2 ov;
                ov.x = acc2[mf][nf][rr * 2 + 0] + bb.x + rv.x;
                ov.y = acc2[mf][nf][rr * 2 + 1] + bb.y + rv.y;
                *(float2*)&out[o] = ov;
            }
        }
}

// ---------------- host launcher ----------------
extern "C" void kernel_launch(void* const* d_in, const int* in_sizes, int n_in,
                              void* d_out, int out_size)
{
    const float* x        = (const float*)d_in[0];
    const float* norm1_g  = (const float*)d_in[1];
    const float* norm1_b  = (const float*)d_in[2];
    const float* qkv_w    = (const float*)d_in[3];
    const float* qkv_b    = (const float*)d_in[4];
    const float* rel_tab  = (const float*)d_in[5];
    const float* proj_w   = (const float*)d_in[6];
    const float* proj_b   = (const float*)d_in[7];
    const float* norm2_g  = (const float*)d_in[8];
    const float* norm2_b  = (const float*)d_in[9];
    const float* fc1_w    = (const float*)d_in[10];
    const float* fc1_b    = (const float*)d_in[11];
    const float* fc2_w    = (const float*)d_in[12];
    const float* fc2_b    = (const float*)d_in[13];
    float* out = (float*)d_out;

    __nv_bfloat16 *attnb, *wT;
    float* x1;
    cudaGetSymbolAddress((void**)&attnb, g_attnb);
    cudaGetSymbolAddress((void**)&wT,    g_wT);
    cudaGetSymbolAddress((void**)&x1,    g_x1);

    const int M = M_TOK;

    cudaFuncSetAttribute(attn_fused, cudaFuncAttributeMaxDynamicSharedMemorySize, ATTF_SMEM);
    cudaFuncSetAttribute(gemm_proj, cudaFuncAttributeMaxDynamicSharedMemorySize, PROJ_SMEM);
    cudaFuncSetAttribute(mlp_fused, cudaFuncAttributeMaxDynamicSharedMemorySize, MLP_SMEM);

    // 0) weights -> bf16 [N,K]
    convert_w_kernel<<<WT_TOTAL / 256, 256>>>(qkv_w, proj_w, fc1_w, fc2_w, wT);

    // 1) fused LN1 + window gather + QKV + attention -> bf16 attnb
    attn_fused<<<M / NTOK, 256, ATTF_SMEM>>>(x, wT + WQ_OFF, norm1_g, norm1_b,
                                             qkv_b, rel_tab, attnb);

    // 2) proj GEMM + reverse/unshift + residual -> fp32 x1
    gemm_proj<<<dim3(1, M / 128), 256, PROJ_SMEM>>>(attnb, wT + WP_OFF, proj_b, x, x1, M, 128, 128);

    // 3) fused MLP: LN2 + FC1 + GELU + FC2 + residual -> fp32 out
    mlp_fused<<<M / 64, 256, MLP_SMEM>>>(x1, wT + W1_OFF, wT + W2_OFF,
                                         norm2_g, norm2_b, fc1_b, fc2_b, out);
}

// round 16
// speedup vs baseline: 1.0383x; 1.0061x over previous
#include <cuda_runtime.h>
#include <cuda_bf16.h>
#include <math.h>
#include <stdint.h>

// ---------------- problem constants ----------------
#define BATCH 64
#define HH 56
#define WW_ 56
#define CDIM 128
#define L_TOK (HH * WW_)            // 3136
#define M_TOK (BATCH * L_TOK)       // 200704
#define NHEAD 4
#define HDIM 32
#define WS 7
#define NWIN_SIDE 8
#define NTOK 49
#define SHIFT 3
#define HIDDEN 512

// weight-transpose buffer offsets (bf16 [N,K] layouts)
#define WQ_OFF 0            // 384*128
#define WP_OFF 49152        // 128*128
#define W1_OFF 65536        // 512*128
#define W2_OFF 131072       // 128*512
#define WT_TOTAL 196608

// ---------------- scratch ----------------
__device__ __nv_bfloat16 g_attnb[(size_t)M_TOK * CDIM];
__device__ float g_x1[(size_t)M_TOK * CDIM];
__device__ __nv_bfloat16 g_wT[WT_TOTAL];

__device__ __forceinline__ uint32_t smem_u32(const void* p) {
    uint32_t a;
    asm("{ .reg .u64 t; cvta.to.shared.u64 t, %1; cvt.u32.u64 %0, t; }" : "=r"(a) : "l"(p));
    return a;
}
__device__ __forceinline__ uint32_t pack_bf2(float a, float b) {
    __nv_bfloat162 t = __floats2bfloat162_rn(a, b);
    return *reinterpret_cast<uint32_t*>(&t);
}
__device__ __forceinline__ void cp16(uint32_t dst, const void* src) {
    asm volatile("cp.async.cg.shared.global [%0], [%1], 16;" :: "r"(dst), "l"(src));
}
#define CP_COMMIT() asm volatile("cp.async.commit_group;" ::: "memory")
#define CP_WAIT(N)  asm volatile("cp.async.wait_group %0;" :: "n"(N) : "memory")

#define LDSM_X4(r0, r1, r2, r3, addr) \
    asm volatile("ldmatrix.sync.aligned.m8n8.x4.shared.b16 {%0,%1,%2,%3}, [%4];" \
        : "=r"(r0), "=r"(r1), "=r"(r2), "=r"(r3) : "r"(addr))

#define LDSM_X4_T(r0, r1, r2, r3, addr) \
    asm volatile("ldmatrix.sync.aligned.m8n8.x4.trans.shared.b16 {%0,%1,%2,%3}, [%4];" \
        : "=r"(r0), "=r"(r1), "=r"(r2), "=r"(r3) : "r"(addr))

#define MMA_BF16(c, a, b0, b1) \
    asm volatile("mma.sync.aligned.m16n8k16.row.col.f32.bf16.bf16.f32 " \
        "{%0,%1,%2,%3}, {%4,%5,%6,%7}, {%8,%9}, {%0,%1,%2,%3};" \
        : "+f"((c)[0]), "+f"((c)[1]), "+f"((c)[2]), "+f"((c)[3]) \
        : "r"((a)[0]), "r"((a)[1]), "r"((a)[2]), "r"((a)[3]), "r"(b0), "r"(b1))

// ---------------- weight transpose + bf16 convert ----------------
__global__ void __launch_bounds__(256) convert_w_kernel(
    const float* __restrict__ qkv_w, const float* __restrict__ proj_w,
    const float* __restrict__ fc1_w, const float* __restrict__ fc2_w,
    __nv_bfloat16* __restrict__ wT)
{
    int i = blockIdx.x * 256 + threadIdx.x;
    if (i < WQ_OFF + 49152) {
        int j = i - WQ_OFF; int n = j / 128, k = j % 128;
        wT[i] = __float2bfloat16(qkv_w[k * 384 + n]);
    } else if (i < WP_OFF + 16384) {
        int j = i - WP_OFF; int n = j / 128, k = j % 128;
        wT[i] = __float2bfloat16(proj_w[k * 128 + n]);
    } else if (i < W1_OFF + 65536) {
        int j = i - W1_OFF; int n = j / 128, k = j % 128;
        wT[i] = __float2bfloat16(fc1_w[k * 512 + n]);
    } else if (i < W2_OFF + 65536) {
        int j = i - W2_OFF; int n = j / 512, k = j % 512;
        wT[i] = __float2bfloat16(fc2_w[k * 128 + n]);
    }
}

// =========================================================================
// Fused front half: LN1(+shift+gather) + QKV + attention.
// V stored row-major; PV uses ldmatrix.trans (no scalar transpose scatter).
// =========================================================================
#define AS 136
#define SPP 72
#define UNI_ELEM 18432
#define ATTF_BASE (64*AS*2 + 36864 + 64*AS*2 + 64*AS*2 + 64*AS*2)
#define ATTF_SMEM (ATTF_BASE + 192 + 2704)

__global__ void __launch_bounds__(256) attn_fused(
    const float* __restrict__ X, const __nv_bfloat16* __restrict__ wq,
    const float* __restrict__ lng, const float* __restrict__ lnb,
    const float* __restrict__ qkvbias, const float* __restrict__ bias_table,
    __nv_bfloat16* __restrict__ out)
{
    extern __shared__ __align__(16) char dsm[];
    __nv_bfloat16* sX  = (__nv_bfloat16*)dsm;
    __nv_bfloat16* uni = sX + 64 * AS;
    __nv_bfloat16* sW  = uni;
    __nv_bfloat16* sP  = uni;
    __nv_bfloat16* sQ  = uni + UNI_ELEM;
    __nv_bfloat16* sK  = sQ + 64 * AS;
    __nv_bfloat16* sV  = sK + 64 * AS;                 // [64][AS] row-major (j, d)
    unsigned char* sGrp = (unsigned char*)(dsm + ATTF_BASE);
    signed char*   sDiv = (signed char*)(sGrp + 64);
    signed char*   sMod = (signed char*)(sDiv + 64);
    float*         sBias = (float*)(dsm + ATTF_BASE + 192);

    const int tid = threadIdx.x, wid = tid >> 5, lane = tid & 31;
    const int win = blockIdx.x;
    const int wloc = win & 63, wh = wloc >> 3, wwi = wloc & 7;

    const int mat = lane >> 3;
    const int aRowOff = (lane & 7) + (mat & 1) * 8;
    const int aKOff = (mat >> 1) * 8;
    const int bRowOff = (lane & 7) + ((mat >> 1) & 1) * 8;
    const int bKOff = (mat & 1) * 8;
    const int g4 = lane >> 2, t4 = lane & 3;

    const uint32_t uX = smem_u32(sX), uW = smem_u32(sW);
    const uint32_t uQ = smem_u32(sQ), uK = smem_u32(sK), uV = smem_u32(sV);

    {
        #pragma unroll
        for (int it = 0; it < 8; ++it) {
            int i = tid + it * 256;
            int r = i >> 4, qq = i & 15;
            cp16(uW + (uint32_t)(r * AS + qq * 8) * 2, wq + (size_t)r * 128 + qq * 8);
        }
        CP_COMMIT();
    }

    for (int i = tid; i < 676; i += 256) sBias[i] = bias_table[i];

    {
        const int row8 = tid >> 3;
        const int lane8 = tid & 7;
        const float4 gv[4] = {
            *(const float4*)&lng[lane8 * 16 + 0],  *(const float4*)&lng[lane8 * 16 + 4],
            *(const float4*)&lng[lane8 * 16 + 8],  *(const float4*)&lng[lane8 * 16 + 12] };
        const float4 bv[4] = {
            *(const float4*)&lnb[lane8 * 16 + 0],  *(const float4*)&lnb[lane8 * 16 + 4],
            *(const float4*)&lnb[lane8 * 16 + 8],  *(const float4*)&lnb[lane8 * 16 + 12] };
        #pragma unroll
        for (int pass = 0; pass < 2; ++pass) {
            const int row = pass * 32 + row8;
            const int trow = (row < NTOK) ? row : (NTOK - 1);
            const int ih = trow / WS, iw = trow - ih * WS;
            int h = wh * WS + ih + SHIFT; if (h >= HH) h -= HH;
            int w = wwi * WS + iw + SHIFT; if (w >= WW_) w -= WW_;
            const int srow = (win >> 6) * L_TOK + h * WW_ + w;
            const float4* xr = (const float4*)(X + (size_t)srow * CDIM) + lane8 * 4;
            float4 v[4];
            float sum = 0.f, sq = 0.f;
            #pragma unroll
            for (int j = 0; j < 4; ++j) {
                v[j] = xr[j];
                sum += v[j].x + v[j].y + v[j].z + v[j].w;
                sq  += v[j].x * v[j].x + v[j].y * v[j].y + v[j].z * v[j].z + v[j].w * v[j].w;
            }
            #pragma unroll
            for (int o = 1; o < 8; o <<= 1) {
                sum += __shfl_xor_sync(0xffffffffu, sum, o);
                sq  += __shfl_xor_sync(0xffffffffu, sq, o);
            }
            const float mean = sum * (1.0f / 128.0f);
            const float var = sq * (1.0f / 128.0f) - mean * mean;
            const float inv = rsqrtf(var + 1e-5f);
            uint4 o0, o1;
            o0.x = pack_bf2((v[0].x - mean) * inv * gv[0].x + bv[0].x,
                            (v[0].y - mean) * inv * gv[0].y + bv[0].y);
            o0.y = pack_bf2((v[0].z - mean) * inv * gv[0].z + bv[0].z,
                            (v[0].w - mean) * inv * gv[0].w + bv[0].w);
            o0.z = pack_bf2((v[1].x - mean) * inv * gv[1].x + bv[1].x,
                            (v[1].y - mean) * inv * gv[1].y + bv[1].y);
            o0.w = pack_bf2((v[1].z - mean) * inv * gv[1].z + bv[1].z,
                            (v[1].w - mean) * inv * gv[1].w + bv[1].w);
            o1.x = pack_bf2((v[2].x - mean) * inv * gv[2].x + bv[2].x,
                            (v[2].y - mean) * inv * gv[2].y + bv[2].y);
            o1.y = pack_bf2((v[2].z - mean) * inv * gv[2].z + bv[2].z,
                            (v[2].w - mean) * inv * gv[2].w + bv[2].w);
            o1.z = pack_bf2((v[3].x - mean) * inv * gv[3].x + bv[3].x,
                            (v[3].y - mean) * inv * gv[3].y + bv[3].y);
            o1.w = pack_bf2((v[3].z - mean) * inv * gv[3].z + bv[3].z,
                            (v[3].w - mean) * inv * gv[3].w + bv[3].w);
            *(uint4*)&sX[row * AS + lane8 * 16 + 0] = o0;
            *(uint4*)&sX[row * AS + lane8 * 16 + 8] = o1;
        }
    }
    if (tid < 64) {
        int ih = tid / 7, iw = tid % 7;
        sDiv[tid] = (signed char)ih;
        sMod[tid] = (signed char)iw;
        int hs = wh * WS + ih, ws = wwi * WS + iw;
        int gh = hs < (HH - WS) ? 0 : (hs < (HH - SHIFT) ? 1 : 2);
        int gw = ws < (WW_ - WS) ? 0 : (ws < (WW_ - SHIFT) ? 1 : 2);
        sGrp[tid] = (unsigned char)(gh * 3 + gw);
    }

    const int mBq = (wid & 1) * 32;
    const int nBq = (wid >> 1) * 32;
    const float scale = 0.17677669529663689f;

    for (int p = 0; p < 3; ++p) {
        CP_WAIT(0);
        __syncthreads();

        float qa[2][4][4];
        #pragma unroll
        for (int i = 0; i < 2; ++i)
            #pragma unroll
            for (int j = 0; j < 4; ++j)
                #pragma unroll
                for (int t = 0; t < 4; ++t) qa[i][j][t] = 0.0f;

        #pragma unroll
        for (int kk = 0; kk < 8; ++kk) {
            const int k0 = kk * 16;
            uint32_t a[2][4];
            #pragma unroll
            for (int mf = 0; mf < 2; ++mf) {
                uint32_t addr = uX + ((mBq + mf * 16 + aRowOff) * AS + k0 + aKOff) * 2;
                LDSM_X4(a[mf][0], a[mf][1], a[mf][2], a[mf][3], addr);
            }
            #pragma unroll
            for (int nn = 0; nn < 2; ++nn) {
                uint32_t b0, b1, b2, b3;
                uint32_t addr = uW + ((nBq + nn * 16 + bRowOff) * AS + k0 + bKOff) * 2;
                LDSM_X4(b0, b1, b2, b3, addr);
                #pragma unroll
                for (int mf = 0; mf < 2; ++mf) {
                    MMA_BF16(qa[mf][nn * 2 + 0], a[mf], b0, b1);
                    MMA_BF16(qa[mf][nn * 2 + 1], a[mf], b2, b3);
                }
            }
        }
        __syncthreads();

        if (p < 2) {
            #pragma unroll
            for (int it = 0; it < 8; ++it) {
                int i = tid + it * 256;
                int r = i >> 4, qq = i & 15;
                cp16(uW + (uint32_t)(r * AS + qq * 8) * 2,
                     wq + (size_t)(p + 1) * 16384 + (size_t)r * 128 + qq * 8);
            }
            CP_COMMIT();
        }

        #pragma unroll
        for (int mf = 0; mf < 2; ++mf)
            #pragma unroll
            for (int rr = 0; rr < 2; ++rr) {
                const int m = mBq + mf * 16 + g4 + rr * 8;
                #pragma unroll
                for (int nf = 0; nf < 4; ++nf) {
                    const int n = nBq + nf * 8 + 2 * t4;
                    const float2 bf2 = *(const float2*)&qkvbias[p * 128 + n];
                    float v0 = qa[mf][nf][rr * 2 + 0] + bf2.x;
                    float v1 = qa[mf][nf][rr * 2 + 1] + bf2.y;
                    if (p == 0) {
                        *(uint32_t*)&sQ[m * AS + n] = pack_bf2(v0 * scale, v1 * scale);
                    } else if (p == 1) {
                        *(uint32_t*)&sK[m * AS + n] = pack_bf2(v0, v1);
                    } else {
                        *(uint32_t*)&sV[m * AS + n] = pack_bf2(v0, v1);
                    }
                }
            }
    }
    __syncthreads();

    const int h = wid >> 1;
    const int mBase = (wid & 1) * 32;
    const int colQ = h * 32;
    __nv_bfloat16* sPw = sP + wid * 32 * SPP;
    const uint32_t uP = smem_u32(sPw);

    float acc[2][8][4];
    #pragma unroll
    for (int i = 0; i < 2; ++i)
        #pragma unroll
        for (int j = 0; j < 8; ++j)
            #pragma unroll
            for (int t = 0; t < 4; ++t) acc[i][j][t] = 0.0f;

    uint32_t a[2][2][4];
    #pragma unroll
    for (int mf = 0; mf < 2; ++mf)
        #pragma unroll
        for (int ks = 0; ks < 2; ++ks) {
            uint32_t addr = uQ + ((mBase + mf * 16 + aRowOff) * AS + colQ + ks * 16 + aKOff) * 2;
            LDSM_X4(a[mf][ks][0], a[mf][ks][1], a[mf][ks][2], a[mf][ks][3], addr);
        }
    #pragma unroll
    for (int nb = 0; nb < 4; ++nb) {
        uint32_t b[2][4];
        #pragma unroll
        for (int ks = 0; ks < 2; ++ks) {
            uint32_t addr = uK + ((nb * 16 + bRowOff) * AS + colQ + ks * 16 + bKOff) * 2;
            LDSM_X4(b[ks][0], b[ks][1], b[ks][2], b[ks][3], addr);
        }
        #pragma unroll
        for (int ks = 0; ks < 2; ++ks)
            #pragma unroll
            for (int mf = 0; mf < 2; ++mf) {
                MMA_BF16(acc[mf][nb * 2 + 0], a[mf][ks], b[ks][0], b[ks][1]);
                MMA_BF16(acc[mf][nb * 2 + 1], a[mf][ks], b[ks][2], b[ks][3]);
            }
    }

    int ii[2][2];
    #pragma unroll
    for (int mf = 0; mf < 2; ++mf)
        #pragma unroll
        for (int rr = 0; rr < 2; ++rr) ii[mf][rr] = mBase + mf * 16 + g4 + rr * 8;

    float mx[2][2] = {{-1e30f, -1e30f}, {-1e30f, -1e30f}};
    #pragma unroll
    for (int mf = 0; mf < 2; ++mf)
        #pragma unroll
        for (int nf = 0; nf < 8; ++nf)
            #pragma unroll
            for (int e = 0; e < 4; ++e) {
                int rr = e >> 1;
                int jj = nf * 8 + 2 * t4 + (e & 1);
                float s;
                if (jj < NTOK) {
                    int i0 = ii[mf][rr];
                    int i0c = (i0 < NTOK) ? i0 : (NTOK - 1);
                    int dh = sDiv[i0c] - sDiv[jj] + 6;
                    int dw = sMod[i0c] - sMod[jj] + 6;
                    float bv = sBias[(dh * 13 + dw) * NHEAD + h];
                    float mk = (sGrp[i0c] != sGrp[jj]) ? -100.0f : 0.0f;
                    s = acc[mf][nf][e] + bv + mk;
                } else {
                    s = -1e30f;
                }
                acc[mf][nf][e] = s;
                mx[mf][rr] = fmaxf(mx[mf][rr], s);
            }
    #pragma unroll
    for (int mf = 0; mf < 2; ++mf)
        #pragma unroll
        for (int rr = 0; rr < 2; ++rr) {
            float m = mx[mf][rr];
            m = fmaxf(m, __shfl_xor_sync(0xffffffffu, m, 1));
            m = fmaxf(m, __shfl_xor_sync(0xffffffffu, m, 2));
            mx[mf][rr] = m;
        }

    float sm[2][2] = {{0.f, 0.f}, {0.f, 0.f}};
    #pragma unroll
    for (int mf = 0; mf < 2; ++mf)
        #pragma unroll
        for (int nf = 0; nf < 8; ++nf)
            #pragma unroll
            for (int e = 0; e < 4; ++e) {
                int rr = e >> 1;
                float ev = __expf(acc[mf][nf][e] - mx[mf][rr]);
                acc[mf][nf][e] = ev;
                sm[mf][rr] += ev;
            }
    #pragma unroll
    for (int mf = 0; mf < 2; ++mf)
        #pragma unroll
        for (int rr = 0; rr < 2; ++rr) {
            float s = sm[mf][rr];
            s += __shfl_xor_sync(0xffffffffu, s, 1);
            s += __shfl_xor_sync(0xffffffffu, s, 2);
            sm[mf][rr] = s;
        }

    #pragma unroll
    for (int mf = 0; mf < 2; ++mf)
        #pragma unroll
        for (int rr = 0; rr < 2; ++rr) {
            int prow = mf * 16 + g4 + rr * 8;
            #pragma unroll
            for (int nf = 0; nf < 8; ++nf) {
                uint32_t u = pack_bf2(acc[mf][nf][rr * 2], acc[mf][nf][rr * 2 + 1]);
                *(uint32_t*)&sPw[prow * SPP + nf * 8 + 2 * t4] = u;
            }
        }
    __syncwarp();

    float acc2[2][4][4];
    #pragma unroll
    for (int i = 0; i < 2; ++i)
        #pragma unroll
        for (int j = 0; j < 4; ++j)
            #pragma unroll
            for (int t = 0; t < 4; ++t) acc2[i][j][t] = 0.0f;

    #pragma unroll
    for (int kc = 0; kc < 4; ++kc) {
        uint32_t a2[2][4], b2[2][4];
        #pragma unroll
        for (int mf = 0; mf < 2; ++mf) {
            uint32_t addr = uP + ((mf * 16 + aRowOff) * SPP + kc * 16 + aKOff) * 2;
            LDSM_X4(a2[mf][0], a2[mf][1], a2[mf][2], a2[mf][3], addr);
        }
        // B from row-major sV via trans ldmatrix:
        // rows = j (k dim): (lane&7) + (mat&1)*8; cols = d (n dim): (mat>>1)*8
        #pragma unroll
        for (int nb = 0; nb < 2; ++nb) {
            uint32_t addr = uV + ((kc * 16 + (lane & 7) + (mat & 1) * 8) * AS
                                  + colQ + nb * 16 + (mat >> 1) * 8) * 2;
            LDSM_X4_T(b2[nb][0], b2[nb][1], b2[nb][2], b2[nb][3], addr);
        }
        #pragma unroll
        for (int mf = 0; mf < 2; ++mf)
            #pragma unroll
            for (int nb = 0; nb < 2; ++nb) {
                MMA_BF16(acc2[mf][nb * 2 + 0], a2[mf], b2[nb][0], b2[nb][1]);
                MMA_BF16(acc2[mf][nb * 2 + 1], a2[mf], b2[nb][2], b2[nb][3]);
            }
    }

    #pragma unroll
    for (int mf = 0; mf < 2; ++mf)
        #pragma unroll
        for (int rr = 0; rr < 2; ++rr) {
            int i0 = ii[mf][rr];
            if (i0 < NTOK) {
                float inv = 1.0f / sm[mf][rr];
                __nv_bfloat16* orow = out + ((size_t)win * NTOK + i0) * CDIM + colQ;
                #pragma unroll
                for (int nf = 0; nf < 4; ++nf) {
                    float v0 = acc2[mf][nf][rr * 2 + 0] * inv;
                    float v1 = acc2[mf][nf][rr * 2 + 1] * inv;
                    *(uint32_t*)&orow[nf * 8 + 2 * t4] = pack_bf2(v0, v1);
                }
            }
        }
}

// =========================================================================
// proj GEMM: K=128 resident, cp.async fill, single sync. (R15)
// =========================================================================
#define SPA 136
#define PROJ_SMEM (2 * 128 * SPA * 2)

__global__ void __launch_bounds__(256) gemm_proj(
    const __nv_bfloat16* __restrict__ A, const __nv_bfloat16* __restrict__ Bt,
    const float* __restrict__ bias, const float* __restrict__ res,
    float* __restrict__ C, int M, int N, int K)
{
    extern __shared__ __align__(16) char dsm[];
    __nv_bfloat16* sA = (__nv_bfloat16*)dsm;
    __nv_bfloat16* sB = sA + 128 * SPA;

    const int tid = threadIdx.x;
    const int wid = tid >> 5, lane = tid & 31;
    const int rowBase = blockIdx.y << 7;

    const int mBase = (wid & 3) * 32;
    const int nBase = (wid >> 2) * 64;

    const uint32_t uA = smem_u32(sA), uB = smem_u32(sB);
    const int mat = lane >> 3;
    const int aRowOff = (lane & 7) + (mat & 1) * 8;
    const int aKOff = (mat >> 1) * 8;
    const int bRowOff = (lane & 7) + ((mat >> 1) & 1) * 8;
    const int bKOff = (mat & 1) * 8;

    {
        const __nv_bfloat16* Ag = A + (size_t)rowBase * CDIM;
        #pragma unroll
        for (int it = 0; it < 8; ++it) {
            int i = tid + it * 256;
            int r = i >> 4, q = i & 15;
            cp16(uA + (uint32_t)(r * SPA + q * 8) * 2, Ag + (size_t)r * CDIM + q * 8);
        }
        #pragma unroll
        for (int it = 0; it < 8; ++it) {
            int i = tid + it * 256;
            int r = i >> 4, q = i & 15;
            cp16(uB + (uint32_t)(r * SPA + q * 8) * 2, Bt + (size_t)r * CDIM + q * 8);
        }
        CP_COMMIT();
    }

    float acc[2][8][4];
    #pragma unroll
    for (int i = 0; i < 2; ++i)
        #pragma unroll
        for (int j = 0; j < 8; ++j)
            #pragma unroll
            for (int t = 0; t < 4; ++t) acc[i][j][t] = 0.0f;

    CP_WAIT(0);
    __syncthreads();

    #pragma unroll
    for (int kk = 0; kk < 8; ++kk) {
        const int k0 = kk * 16;
        uint32_t a[2][4];
        #pragma unroll
        for (int mf = 0; mf < 2; ++mf) {
            uint32_t addr = uA + ((mBase + mf * 16 + aRowOff) * SPA + k0 + aKOff) * 2;
            LDSM_X4(a[mf][0], a[mf][1], a[mf][2], a[mf][3], addr);
        }
        #pragma unroll
        for (int nn = 0; nn < 4; ++nn) {
            uint32_t b0, b1, b2, b3;
            uint32_t addr = uB + ((nBase + nn * 16 + bRowOff) * SPA + k0 + bKOff) * 2;
            LDSM_X4(b0, b1, b2, b3, addr);
            #pragma unroll
            for (int mf = 0; mf < 2; ++mf) {
                MMA_BF16(acc[mf][nn * 2 + 0], a[mf], b0, b1);
                MMA_BF16(acc[mf][nn * 2 + 1], a[mf], b2, b3);
            }
        }
    }

    const int g4 = lane >> 2, t4 = lane & 3;
    #pragma unroll
    for (int mf = 0; mf < 2; ++mf)
        #pragma unroll
        for (int rr = 0; rr < 2; ++rr) {
            const int m = rowBase + mBase + mf * 16 + g4 + rr * 8;
            int win = m / NTOK, tt = m - win * NTOK;
            int bimg = win >> 6, wloc = win & 63;
            int wh = wloc >> 3, wwi = wloc & 7;
            int ih = tt / WS, iw = tt - ih * WS;
            int h = wh * WS + ih + SHIFT; if (h >= HH) h -= HH;
            int w = wwi * WS + iw + SHIFT; if (w >= WW_) w -= WW_;
            const int prow = bimg * L_TOK + h * WW_ + w;
            #pragma unroll
            for (int nf = 0; nf < 8; ++nf) {
                const int col = nBase + nf * 8 + 2 * t4;
                const float2 bf2 = *(const float2*)&bias[col];
                float v0 = acc[mf][nf][rr * 2 + 0] + bf2.x;
                float v1 = acc[mf][nf][rr * 2 + 1] + bf2.y;
                const size_t o = (size_t)prow * CDIM + col;
                float2 rv = *(const float2*)&res[o];
                float2 ov; ov.x = v0 + rv.x; ov.y = v1 + rv.y;
                *(float2*)&C[o] = ov;
            }
        }
}

// =========================================================================
// Fused MLP: LN2 + FC1 + GELU + FC2 + residual, cp.async pipelined. (R13)
// =========================================================================
#define SMX 136
#define MLP_SMEM ((64 + 64 + 128 + 128) * SMX * 2)

__global__ void __launch_bounds__(256) mlp_fused(
    const float* __restrict__ X, const __nv_bfloat16* __restrict__ w1T,
    const __nv_bfloat16* __restrict__ w2T,
    const float* __restrict__ lng, const float* __restrict__ lnb,
    const float* __restrict__ b1, const float* __restrict__ b2,
    float* __restrict__ out)
{
    extern __shared__ __align__(16) char dsm[];
    __nv_bfloat16* sX  = (__nv_bfloat16*)dsm;
    __nv_bfloat16* sH  = sX + 64 * SMX;
    __nv_bfloat16* sW1 = sH + 64 * SMX;
    __nv_bfloat16* sW2 = sW1 + 128 * SMX;

    const int tid = threadIdx.x;
    const int wid = tid >> 5, lane = tid & 31;
    const int rowBase = blockIdx.x << 6;

    const uint32_t uX = smem_u32(sX), uH = smem_u32(sH);
    const uint32_t uW1 = smem_u32(sW1), uW2 = smem_u32(sW2);

    {
        #pragma unroll
        for (int it = 0; it < 8; ++it) {
            int i = tid + it * 256;
            int r = i >> 4, q = i & 15;
            cp16(uW1 + (uint32_t)(r * SMX + q * 8) * 2, w1T + (size_t)r * 128 + q * 8);
        }
        CP_COMMIT();
        #pragma unroll
        for (int it = 0; it < 8; ++it) {
            int i = tid + it * 256;
            int r = i >> 4, q = i & 15;
            cp16(uW2 + (uint32_t)(r * SMX + q * 8) * 2, w2T + (size_t)r * 512 + q * 8);
        }
        CP_COMMIT();
    }

    // ---- LN2 on 64 token rows ----
    {
        const int row8 = tid >> 3;
        const int lane8 = tid & 7;
        const float4 gv[4] = {
            *(const float4*)&lng[lane8 * 16 + 0],  *(const float4*)&lng[lane8 * 16 + 4],
            *(const float4*)&lng[lane8 * 16 + 8],  *(const float4*)&lng[lane8 * 16 + 12] };
        const float4 bv[4] = {
            *(const float4*)&lnb[lane8 * 16 + 0],  *(const float4*)&lnb[lane8 * 16 + 4],
            *(const float4*)&lnb[lane8 * 16 + 8],  *(const float4*)&lnb[lane8 * 16 + 12] };
        #pragma unroll
        for (int pass = 0; pass < 2; ++pass) {
            const int row = pass * 32 + row8;
            const float4* xr = (const float4*)(X + (size_t)(rowBase + row) * CDIM) + lane8 * 4;
            float4 v[4];
            float sum = 0.f, sq = 0.f;
            #pragma unroll
            for (int j = 0; j < 4; ++j) {
                v[j] = xr[j];
                sum += v[j].x + v[j].y + v[j].z + v[j].w;
                sq  += v[j].x * v[j].x + v[j].y * v[j].y + v[j].z * v[j].z + v[j].w * v[j].w;
            }
            #pragma unroll
            for (int o = 1; o < 8; o <<= 1) {
                sum += __shfl_xor_sync(0xffffffffu, sum, o);
                sq  += __shfl_xor_sync(0xffffffffu, sq, o);
            }
            const float mean = sum * (1.0f / 128.0f);
            const float var = sq * (1.0f / 128.0f) - mean * mean;
            const float inv = rsqrtf(var + 1e-5f);
            uint4 o0, o1;
            o0.x = pack_bf2((v[0].x - mean) * inv * gv[0].x + bv[0].x,
                            (v[0].y - mean) * inv * gv[0].y + bv[0].y);
            o0.y = pack_bf2((v[0].z - mean) * inv * gv[0].z + bv[0].z,
                            (v[0].w - mean) * inv * gv[0].w + bv[0].w);
            o0.z = pack_bf2((v[1].x - mean) * inv * gv[1].x + bv[1].x,
                            (v[1].y - mean) * inv * gv[1].y + bv[1].y);
            o0.w = pack_bf2((v[1].z - mean) * inv * gv[1].z + bv[1].z,
                            (v[1].w - mean) * inv * gv[1].w + bv[1].w);
            o1.x = pack_bf2((v[2].x - mean) * inv * gv[2].x + bv[2].x,
                            (v[2].y - mean) * inv * gv[2].y + bv[2].y);
            o1.y = pack_bf2((v[2].z - mean) * inv * gv[2].z + bv[2].z,
                            (v[2].w - mean) * inv * gv[2].w + bv[2].w);
            o1.z = pack_bf2((v[3].x - mean) * inv * gv[3].x + bv[3].x,
                            (v[3].y - mean) * inv * gv[3].y + bv[3].y);
            o1.w = pack_bf2((v[3].z - mean) * inv * gv[3].z + bv[3].z,
                            (v[3].w - mean) * inv * gv[3].w + bv[3].w);
            *(uint4*)&sX[row * SMX + lane8 * 16 + 0] = o0;
            *(uint4*)&sX[row * SMX + lane8 * 16 + 8] = o1;
        }
    }

    const int mBase = (wid & 1) * 32;
    const int nBase = (wid >> 1) * 32;

    const int mat = lane >> 3;
    const int aRowOff = (lane & 7) + (mat & 1) * 8;
    const int aKOff = (mat >> 1) * 8;
    const int bRowOff = (lane & 7) + ((mat >> 1) & 1) * 8;
    const int bKOff = (mat & 1) * 8;
    const int g4 = lane >> 2, t4 = lane & 3;

    float acc2[2][4][4];
    #pragma unroll
    for (int i = 0; i < 2; ++i)
        #pragma unroll
        for (int j = 0; j < 4; ++j)
            #pragma unroll
            for (int t = 0; t < 4; ++t) acc2[i][j][t] = 0.0f;

    for (int c = 0; c < 4; ++c) {
        CP_WAIT(1);
        __syncthreads();

        float hacc[2][4][4];
        #pragma unroll
        for (int i = 0; i < 2; ++i)
            #pragma unroll
            for (int j = 0; j < 4; ++j)
                #pragma unroll
                for (int t = 0; t < 4; ++t) hacc[i][j][t] = 0.0f;

        #pragma unroll
        for (int kk = 0; kk < 8; ++kk) {
            const int k0 = kk * 16;
            uint32_t a[2][4];
            #pragma unroll
            for (int mf = 0; mf < 2; ++mf) {
                uint32_t addr = uX + ((mBase + mf * 16 + aRowOff) * SMX + k0 + aKOff) * 2;
                LDSM_X4(a[mf][0], a[mf][1], a[mf][2], a[mf][3], addr);
            }
            #pragma unroll
            for (int nn = 0; nn < 2; ++nn) {
                uint32_t b0, b1, b2, b3;
                uint32_t addr = uW1 + ((nBase + nn * 16 + bRowOff) * SMX + k0 + bKOff) * 2;
                LDSM_X4(b0, b1, b2, b3, addr);
                #pragma unroll
                for (int mf = 0; mf < 2; ++mf) {
                    MMA_BF16(hacc[mf][nn * 2 + 0], a[mf], b0, b1);
                    MMA_BF16(hacc[mf][nn * 2 + 1], a[mf], b2, b3);
                }
            }
        }
        __syncthreads();

        if (c < 3) {
            #pragma unroll
            for (int it = 0; it < 8; ++it) {
                int i = tid + it * 256;
                int r = i >> 4, q = i & 15;
                cp16(uW1 + (uint32_t)(r * SMX + q * 8) * 2,
                     w1T + (size_t)(c + 1) * 16384 + (size_t)r * 128 + q * 8);
            }
            CP_COMMIT();
        }

        #pragma unroll
        for (int mf = 0; mf < 2; ++mf)
            #pragma unroll
            for (int rr = 0; rr < 2; ++rr) {
                const int hrow = mBase + mf * 16 + g4 + rr * 8;
                #pragma unroll
                for (int nf = 0; nf < 4; ++nf) {
                    const int hcol = nBase + nf * 8 + 2 * t4;
                    const float2 bb = *(const float2*)&b1[c * 128 + hcol];
                    float v0 = hacc[mf][nf][rr * 2 + 0] + bb.x;
                    float v1 = hacc[mf][nf][rr * 2 + 1] + bb.y;
                    v0 = 0.5f * v0 * (1.0f + erff(v0 * 0.70710678118654752f));
                    v1 = 0.5f * v1 * (1.0f + erff(v1 * 0.70710678118654752f));
                    *(uint32_t*)&sH[hrow * SMX + hcol] = pack_bf2(v0, v1);
                }
            }
        if (c < 3) {
            CP_WAIT(1);
        } else {
            CP_WAIT(0);
        }
        __syncthreads();

        #pragma unroll
        for (int kk = 0; kk < 8; ++kk) {
            const int k0 = kk * 16;
            uint32_t a[2][4];
            #pragma unroll
            for (int mf = 0; mf < 2; ++mf) {
                uint32_t addr = uH + ((mBase + mf * 16 + aRowOff) * SMX + k0 + aKOff) * 2;
                LDSM_X4(a[mf][0], a[mf][1], a[mf][2], a[mf][3], addr);
            }
            #pragma unroll
            for (int nn = 0; nn < 2; ++nn) {
                uint32_t b0, b1, b2, b3;
                uint32_t addr = uW2 + ((nBase + nn * 16 + bRowOff) * SMX + k0 + bKOff) * 2;
                LDSM_X4(b0, b1, b2, b3, addr);
                #pragma unroll
                for (int mf = 0; mf < 2; ++mf) {
                    MMA_BF16(acc2[mf][nn * 2 + 0], a[mf], b0, b1);
                    MMA_BF16(acc2[mf][nn * 2 + 1], a[mf], b2, b3);
                }
            }
        }
        __syncthreads();

        if (c < 3) {
            #pragma unroll
            for (int it = 0; it < 8; ++it) {
                int i = tid + it * 256;
                int r = i >> 4, q = i & 15;
                cp16(uW2 + (uint32_t)(r * SMX + q * 8) * 2,
                     w2T + (size_t)r * 512 + (size_t)(c + 1) * 128 + q * 8);
            }
            CP_COMMIT();
        }
    }

    #pragma unroll
    for (int mf = 0; mf < 2; ++mf)
        #pragma unroll
        for (int rr = 0; rr < 2; ++rr) {
            const int m = rowBase + mBase + mf * 16 + g4 + rr * 8;
            #pragma unroll
            for (int nf = 0; nf < 4; ++nf) {
                const int col = nBase + nf * 8 + 2 * t4;
                const size_t o = (size_t)m * CDIM + col;
                const float2 bb = *(const float2*)&b2[col];
                float2 rv = *(const float2*)&X[o];
                float2 ov;
                ov.x = acc2[mf][nf][rr * 2 + 0] + bb.x + rv.x;
                ov.y = acc2[mf][nf][rr * 2 + 1] + bb.y + rv.y;
                *(float2*)&out[o] = ov;
            }
        }
}

// ---------------- host launcher ----------------
extern "C" void kernel_launch(void* const* d_in, const int* in_sizes, int n_in,
                              void* d_out, int out_size)
{
    const float* x        = (const float*)d_in[0];
    const float* norm1_g  = (const float*)d_in[1];
    const float* norm1_b  = (const float*)d_in[2];
    const float* qkv_w    = (const float*)d_in[3];
    const float* qkv_b    = (const float*)d_in[4];
    const float* rel_tab  = (const float*)d_in[5];
    const float* proj_w   = (const float*)d_in[6];
    const float* proj_b   = (const float*)d_in[7];
    const float* norm2_g  = (const float*)d_in[8];
    const float* norm2_b  = (const float*)d_in[9];
    const float* fc1_w    = (const float*)d_in[10];
    const float* fc1_b    = (const float*)d_in[11];
    const float* fc2_w    = (const float*)d_in[12];
    const float* fc2_b    = (const float*)d_in[13];
    float* out = (float*)d_out;

    __nv_bfloat16 *attnb, *wT;
    float* x1;
    cudaGetSymbolAddress((void**)&attnb, g_attnb);
    cudaGetSymbolAddress((void**)&wT,    g_wT);
    cudaGetSymbolAddress((void**)&x1,    g_x1);

    const int M = M_TOK;

    cudaFuncSetAttribute(attn_fused, cudaFuncAttributeMaxDynamicSharedMemorySize, ATTF_SMEM);
    cudaFuncSetAttribute(gemm_proj, cudaFuncAttributeMaxDynamicSharedMemorySize, PROJ_SMEM);
    cudaFuncSetAttribute(mlp_fused, cudaFuncAttributeMaxDynamicSharedMemorySize, MLP_SMEM);

    // 0) weights -> bf16 [N,K]
    convert_w_kernel<<<WT_TOTAL / 256, 256>>>(qkv_w, proj_w, fc1_w, fc2_w, wT);

    // 1) fused LN1 + window gather + QKV + attention -> bf16 attnb
    attn_fused<<<M / NTOK, 256, ATTF_SMEM>>>(x, wT + WQ_OFF, norm1_g, norm1_b,
                                             qkv_b, rel_tab, attnb);

    // 2) proj GEMM + reverse/unshift + residual -> fp32 x1
    gemm_proj<<<dim3(1, M / 128), 256, PROJ_SMEM>>>(attnb, wT + WP_OFF, proj_b, x, x1, M, 128, 128);

    // 3) fused MLP: LN2 + FC1 + GELU + FC2 + residual -> fp32 out
    mlp_fused<<<M / 64, 256, MLP_SMEM>>>(x1, wT + W1_OFF, wT + W2_OFF,
                                         norm2_g, norm2_b, fc1_b, fc2_b, out);
}